// round 11
// baseline (speedup 1.0000x reference)
#include <cuda_runtime.h>
#include <cuda_bf16.h>
#include <cstdint>

#define EDIM  1024
#define HEADS 16
#define HD    64
#define WIN   256
#define BATCH 2
#define SEQ   2048
#define MROWS (BATCH*SEQ)   // 4096

// ---------------- scratch (allocation-free rule: device globals) ----------------
static __device__ __nv_bfloat16 g_xh[MROWS*EDIM];
static __device__ __nv_bfloat16 g_xl[MROWS*EDIM];
static __device__ __nv_bfloat16 g_qh[MROWS*EDIM];
static __device__ __nv_bfloat16 g_ql[MROWS*EDIM];
static __device__ __nv_bfloat16 g_kh[MROWS*EDIM];
static __device__ __nv_bfloat16 g_kl[MROWS*EDIM];
static __device__ __nv_bfloat16 g_vh[MROWS*EDIM];
static __device__ __nv_bfloat16 g_vl[MROWS*EDIM];
static __device__ __nv_bfloat16 g_yh[MROWS*EDIM];
static __device__ __nv_bfloat16 g_yl[MROWS*EDIM];
static __device__ __nv_bfloat16 g_wh[4][EDIM*EDIM];
static __device__ __nv_bfloat16 g_wl[4][EDIM*EDIM];

// ---------------- family-common PTX helpers ----------------
__device__ __forceinline__ uint32_t smem_to_u32(const void* p) {
    uint32_t a;
    asm("{ .reg .u64 t; cvta.to.shared.u64 t, %1; cvt.u32.u64 %0, t; }"
        : "=r"(a) : "l"(p));
    return a;
}
__device__ __forceinline__ void cp_async16(uint32_t dst, const void* src) {
    asm volatile("cp.async.cg.shared.global [%0], [%1], 16;" :: "r"(dst), "l"(src));
}
#define CP_COMMIT() asm volatile("cp.async.commit_group;" ::: "memory")
#define CP_WAIT1()  asm volatile("cp.async.wait_group 1;" ::: "memory")
#define CP_WAIT0()  asm volatile("cp.async.wait_group 0;" ::: "memory")

__device__ __forceinline__ void ldsm4(uint32_t& r0, uint32_t& r1, uint32_t& r2,
                                      uint32_t& r3, uint32_t addr) {
    asm volatile("ldmatrix.sync.aligned.m8n8.x4.shared.b16 {%0,%1,%2,%3}, [%4];"
                 : "=r"(r0), "=r"(r1), "=r"(r2), "=r"(r3) : "r"(addr));
}
__device__ __forceinline__ void ldsm4t(uint32_t& r0, uint32_t& r1, uint32_t& r2,
                                       uint32_t& r3, uint32_t addr) {
    asm volatile("ldmatrix.sync.aligned.m8n8.x4.trans.shared.b16 {%0,%1,%2,%3}, [%4];"
                 : "=r"(r0), "=r"(r1), "=r"(r2), "=r"(r3) : "r"(addr));
}
__device__ __forceinline__ void mma16816(float* c, uint32_t a0, uint32_t a1,
                                         uint32_t a2, uint32_t a3,
                                         uint32_t b0, uint32_t b1) {
    asm volatile(
        "mma.sync.aligned.m16n8k16.row.col.f32.bf16.bf16.f32 "
        "{%0,%1,%2,%3}, {%4,%5,%6,%7}, {%8,%9}, {%0,%1,%2,%3};"
        : "+f"(c[0]), "+f"(c[1]), "+f"(c[2]), "+f"(c[3])
        : "r"(a0), "r"(a1), "r"(a2), "r"(a3), "r"(b0), "r"(b1));
}
__device__ __forceinline__ uint32_t packbf2(float a, float b) {
    __nv_bfloat162 t = __floats2bfloat162_rn(a, b);
    return *(uint32_t*)&t;
}

// ---------------- fused fp32 -> bf16 hi/lo split (5 tensors, one launch) -------
__global__ __launch_bounds__(256)
void split5(const float* __restrict__ s0, const float* __restrict__ s1,
            const float* __restrict__ s2, const float* __restrict__ s3,
            const float* __restrict__ s4,
            __nv_bfloat16* __restrict__ h0, __nv_bfloat16* __restrict__ l0,
            __nv_bfloat16* __restrict__ h1, __nv_bfloat16* __restrict__ l1,
            __nv_bfloat16* __restrict__ h2, __nv_bfloat16* __restrict__ l2,
            __nv_bfloat16* __restrict__ h3, __nv_bfloat16* __restrict__ l3,
            __nv_bfloat16* __restrict__ h4, __nv_bfloat16* __restrict__ l4,
            int n0, int nw)
{
    const int t = blockIdx.y;
    const int n4 = (t == 0) ? n0 : nw;
    int i = blockIdx.x * 256 + threadIdx.x;
    if (i >= n4) return;
    const float* in = (t == 0) ? s0 : (t == 1) ? s1 : (t == 2) ? s2 : (t == 3) ? s3 : s4;
    __nv_bfloat16* hi = (t == 0) ? h0 : (t == 1) ? h1 : (t == 2) ? h2 : (t == 3) ? h3 : h4;
    __nv_bfloat16* lo = (t == 0) ? l0 : (t == 1) ? l1 : (t == 2) ? l2 : (t == 3) ? l3 : l4;
    float4 v = ((const float4*)in)[i];
    float vv[4] = {v.x, v.y, v.z, v.w};
    __nv_bfloat16 h[4], l[4];
#pragma unroll
    for (int j = 0; j < 4; j++) {
        h[j] = __float2bfloat16_rn(vv[j]);
        l[j] = __float2bfloat16_rn(vv[j] - __bfloat162float(h[j]));
    }
    ((uint2*)hi)[i] = *(uint2*)h;
    ((uint2*)lo)[i] = *(uint2*)l;
}

// ---------------- bf16 warp-MMA GEMM, fused 4-tile 3-pass split ----------------
// C[256x128 per CTA] = scale * (Ah@Wh^T + Ah@Wl^T + Al@Wh^T + bias)
// 8 warps each 64x64. BKC=32, THREE smem stages, prefetch depth 2
// (load of chunk c has ~2 compute-chunks to complete -> latency hidden).
#define BM   256
#define BN   128
#define BKC  32
#define LDSB 40                          // 32 cols + 8 pad (conflict-free ldsm)
#define A2OFF (256*LDSB)
#define WHOFF (512*LDSB)
#define WLOFF (640*LDSB)
#define STAGE (768*LDSB)                 // elements per stage (30720)
#define GEMM_SMEM (3*STAGE*2)            // 184,320 B -> 1 CTA/SM, 8 warps

__global__ __launch_bounds__(256, 1)
void gemm_tc3(const __nv_bfloat16* __restrict__ Ah, const __nv_bfloat16* __restrict__ Al,
              const __nv_bfloat16* __restrict__ Wh, const __nv_bfloat16* __restrict__ Wl,
              const float* __restrict__ b0v, const float* __restrict__ b1v,
              const float* __restrict__ b2v,
              float* __restrict__ Cf,
              __nv_bfloat16* __restrict__ H0, __nv_bfloat16* __restrict__ L0,
              __nv_bfloat16* __restrict__ H1, __nv_bfloat16* __restrict__ L1,
              __nv_bfloat16* __restrict__ H2, __nv_bfloat16* __restrict__ L2,
              float s0, int bf16out)
{
    extern __shared__ __align__(16) __nv_bfloat16 gsm[];

    const int tid  = threadIdx.x;
    const int wid  = tid >> 5;
    const int lane = tid & 31;
    const int bm   = blockIdx.y * BM;
    const int bn   = blockIdx.x * BN;
    const int z    = blockIdx.z;
    const int wm   = (wid & 3) * 64;     // 4 m-slabs of 64
    const int wn   = (wid >> 2) * 64;    // 2 n-slabs of 64

    const __nv_bfloat16* Whb = Wh + (size_t)z * EDIM * EDIM + (size_t)bn * EDIM;
    const __nv_bfloat16* Wlb = Wl + (size_t)z * EDIM * EDIM + (size_t)bn * EDIM;
    const __nv_bfloat16* Ahb = Ah + (size_t)bm * EDIM;
    const __nv_bfloat16* Alb = Al + (size_t)bm * EDIM;
    const float* bias = (z == 0) ? b0v : (z == 1) ? b1v : b2v;
    const float scale = (z == 0) ? s0 : 1.0f;

    float acc[4][8][4];
#pragma unroll
    for (int mt = 0; mt < 4; mt++)
#pragma unroll
        for (int nt = 0; nt < 8; nt++)
#pragma unroll
            for (int j = 0; j < 4; j++) acc[mt][nt][j] = 0.f;

    const int a_row = lane & 15, a_ch = lane >> 4;
    const int b_nin = (lane & 7) + ((lane >= 16) ? 8 : 0);
    const int b_ch  = (lane >> 3) & 1;

// one chunk (k32): Ah,Al 256x32 (4 segs/thread each), Wh,Wl 128x32 (2 each)
#define LOADC(cc, st) do { \
    const int _kc = (cc); \
    __nv_bfloat16* _sa = gsm + (st) * STAGE; \
    const __nv_bfloat16* _ah = Ahb + (size_t)_kc * BKC; \
    const __nv_bfloat16* _al = Alb + (size_t)_kc * BKC; \
    const __nv_bfloat16* _wh = Whb + (size_t)_kc * BKC; \
    const __nv_bfloat16* _wl = Wlb + (size_t)_kc * BKC; \
    _Pragma("unroll") \
    for (int _i = 0; _i < 4; _i++) { \
        int _idx = tid + _i * 256; int _r = _idx >> 2, _s = _idx & 3; \
        cp_async16(smem_to_u32(&_sa[_r * LDSB + _s * 8]), _ah + (size_t)_r * EDIM + _s * 8); \
        cp_async16(smem_to_u32(&_sa[A2OFF + _r * LDSB + _s * 8]), _al + (size_t)_r * EDIM + _s * 8); \
    } \
    _Pragma("unroll") \
    for (int _i = 0; _i < 2; _i++) { \
        int _idx = tid + _i * 256; int _r = _idx >> 2, _s = _idx & 3; \
        cp_async16(smem_to_u32(&_sa[WHOFF + _r * LDSB + _s * 8]), _wh + (size_t)_r * EDIM + _s * 8); \
        cp_async16(smem_to_u32(&_sa[WLOFF + _r * LDSB + _s * 8]), _wl + (size_t)_r * EDIM + _s * 8); \
    } \
} while (0)

    const int NCH = EDIM / BKC;          // 32
    LOADC(0, 0); CP_COMMIT();
    LOADC(1, 1); CP_COMMIT();

    for (int c = 0; c < NCH; c++) {
        if (c + 1 < NCH) CP_WAIT1(); else CP_WAIT0();
        __syncthreads();
        if (c + 2 < NCH) { LOADC(c + 2, (c + 2) % 3); CP_COMMIT(); }

        const __nv_bfloat16* st = gsm + (c % 3) * STAGE;
#pragma unroll
        for (int ks = 0; ks < 2; ks++) {
            const int k0 = ks * 16;
            // W fragments for this ks (shared across all 4 m-slabs)
            uint32_t whf[8][2], wlf[8][2];
#pragma unroll
            for (int p = 0; p < 4; p++) {
                uint32_t base = (wn + p * 16 + b_nin) * LDSB + k0 + b_ch * 8;
                uint32_t r0, r1, r2, r3;
                ldsm4(r0, r1, r2, r3, smem_to_u32(&st[WHOFF + base]));
                whf[2*p][0] = r0; whf[2*p][1] = r1; whf[2*p+1][0] = r2; whf[2*p+1][1] = r3;
                ldsm4(r0, r1, r2, r3, smem_to_u32(&st[WLOFF + base]));
                wlf[2*p][0] = r0; wlf[2*p][1] = r1; wlf[2*p+1][0] = r2; wlf[2*p+1][1] = r3;
            }
            // per m-slab: load its A frags, run its 3 passes (small live window)
#pragma unroll
            for (int mt = 0; mt < 4; mt++) {
                uint32_t ahf[4], alf[4];
                uint32_t base = (wm + mt * 16 + a_row) * LDSB + k0 + a_ch * 8;
                ldsm4(ahf[0], ahf[1], ahf[2], ahf[3], smem_to_u32(&st[base]));
                ldsm4(alf[0], alf[1], alf[2], alf[3], smem_to_u32(&st[A2OFF + base]));
#pragma unroll
                for (int nt = 0; nt < 8; nt++)
                    mma16816(acc[mt][nt], ahf[0], ahf[1], ahf[2], ahf[3],
                             whf[nt][0], whf[nt][1]);
#pragma unroll
                for (int nt = 0; nt < 8; nt++)
                    mma16816(acc[mt][nt], ahf[0], ahf[1], ahf[2], ahf[3],
                             wlf[nt][0], wlf[nt][1]);
#pragma unroll
                for (int nt = 0; nt < 8; nt++)
                    mma16816(acc[mt][nt], alf[0], alf[1], alf[2], alf[3],
                             whf[nt][0], whf[nt][1]);
            }
        }
    }
#undef LOADC

    if (bf16out) {
        __nv_bfloat16* H = (z == 0) ? H0 : (z == 1) ? H1 : H2;
        __nv_bfloat16* L = (z == 0) ? L0 : (z == 1) ? L1 : L2;
#pragma unroll
        for (int nt = 0; nt < 8; nt++) {
            const int col = bn + wn + nt * 8 + (lane & 3) * 2;
            const float c0 = bias[col], c1 = bias[col + 1];
#pragma unroll
            for (int mt = 0; mt < 4; mt++) {
                const int r0 = bm + wm + mt * 16 + (lane >> 2);
#pragma unroll
                for (int rr = 0; rr < 2; rr++) {
                    float vx = (acc[mt][nt][2*rr+0] + c0) * scale;
                    float vy = (acc[mt][nt][2*rr+1] + c1) * scale;
                    __nv_bfloat16 hx = __float2bfloat16_rn(vx);
                    __nv_bfloat16 hy = __float2bfloat16_rn(vy);
                    float lx = vx - __bfloat162float(hx);
                    float ly = vy - __bfloat162float(hy);
                    size_t off = (size_t)(r0 + rr*8) * EDIM + col;
                    *(uint32_t*)(H + off) = ((uint32_t)*(uint16_t*)&hy << 16) | *(uint16_t*)&hx;
                    *(uint32_t*)(L + off) = packbf2(lx, ly);
                }
            }
        }
    } else {
#pragma unroll
        for (int nt = 0; nt < 8; nt++) {
            const int col = bn + wn + nt * 8 + (lane & 3) * 2;
            const float c0 = bias[col], c1 = bias[col + 1];
#pragma unroll
            for (int mt = 0; mt < 4; mt++) {
                const int r0 = bm + wm + mt * 16 + (lane >> 2);
                *(float2*)&Cf[(size_t)r0 * EDIM + col] =
                    make_float2((acc[mt][nt][0] + c0) * scale, (acc[mt][nt][1] + c1) * scale);
                *(float2*)&Cf[(size_t)(r0 + 8) * EDIM + col] =
                    make_float2((acc[mt][nt][2] + c0) * scale, (acc[mt][nt][3] + c1) * scale);
            }
        }
    }
}

// ---------------- sliding-window flash attention, bf16-split warp MMA ----------------
#define ALDA 72
#define ATT_SMEM ((2*64 + 2*4*64) * ALDA * 2)   // 92160 B

__global__ __launch_bounds__(128)
void swattn_tc(const __nv_bfloat16* __restrict__ Qh, const __nv_bfloat16* __restrict__ Ql,
               const __nv_bfloat16* __restrict__ Kh, const __nv_bfloat16* __restrict__ Kl,
               const __nv_bfloat16* __restrict__ Vh, const __nv_bfloat16* __restrict__ Vl,
               __nv_bfloat16* __restrict__ Oh, __nv_bfloat16* __restrict__ Ol)
{
    extern __shared__ __align__(16) __nv_bfloat16 sb[];
    __nv_bfloat16* Qsh = sb;
    __nv_bfloat16* Qsl = Qsh + 64 * ALDA;
    __nv_bfloat16* KV  = Qsl + 64 * ALDA;     // [buf][4][64*ALDA]

    const int tid = threadIdx.x, wid = tid >> 5, lane = tid & 31;
    const int qt = blockIdx.x, h = blockIdx.y, b = blockIdx.z;
    const int q0 = qt * 64;
    const size_t base = (size_t)b * SEQ * EDIM + (size_t)h * HD;
    const int kb0 = (qt > 4) ? qt - 4 : 0;
    const int NB  = qt - kb0 + 1;

    {
        const __nv_bfloat16* qs[2] = {Qh, Ql};
        __nv_bfloat16* qd[2] = {Qsh, Qsl};
#pragma unroll
        for (int i = 0; i < 8; i++) {
            int idx = tid + i * 128;
            int t = idx >> 9, r = (idx >> 3) & 63, s = idx & 7;
            cp_async16(smem_to_u32(qd[t] + r * ALDA + s * 8),
                       qs[t] + base + (size_t)(q0 + r) * EDIM + s * 8);
        }
    }
    CP_COMMIT();

#define ALOAD_KV(kb, buf) do { \
    const __nv_bfloat16* _srcs[4] = {Kh, Kl, Vh, Vl}; \
    __nv_bfloat16* _d = KV + (buf) * 4 * 64 * ALDA; \
    _Pragma("unroll") \
    for (int _i = 0; _i < 16; _i++) { \
        int _idx = tid + _i * 128; \
        int _t = _idx >> 9, _r = (_idx >> 3) & 63, _s = _idx & 7; \
        cp_async16(smem_to_u32(_d + _t * 64 * ALDA + _r * ALDA + _s * 8), \
                   _srcs[_t] + base + (size_t)((kb) * 64 + _r) * EDIM + _s * 8); \
    } \
} while (0)

    ALOAD_KV(kb0, 0); CP_COMMIT();
    if (NB >= 2) { ALOAD_KV(kb0 + 1, 1); CP_COMMIT(); }

    const int b_nin = (lane & 7) + ((lane >= 16) ? 8 : 0);
    const int b_ch  = (lane >> 3) & 1;

    uint32_t qhf[4][4], qlf[4][4];
    float o[8][4];
#pragma unroll
    for (int nt = 0; nt < 8; nt++)
#pragma unroll
        for (int j = 0; j < 4; j++) o[nt][j] = 0.f;
    float m0 = -1e30f, m1 = -1e30f, l0 = 0.f, l1 = 0.f;
    const int i0 = q0 + wid * 16 + (lane >> 2);

    for (int j = 0; j < NB; j++) {
        if (j + 1 < NB) CP_WAIT1(); else CP_WAIT0();
        __syncthreads();
        if (j == 0) {
#pragma unroll
            for (int kt = 0; kt < 4; kt++) {
                uint32_t ah = smem_to_u32(&Qsh[(wid*16 + (lane & 15)) * ALDA + kt*16 + (lane >> 4)*8]);
                uint32_t al = smem_to_u32(&Qsl[(wid*16 + (lane & 15)) * ALDA + kt*16 + (lane >> 4)*8]);
                ldsm4(qhf[kt][0], qhf[kt][1], qhf[kt][2], qhf[kt][3], ah);
                ldsm4(qlf[kt][0], qlf[kt][1], qlf[kt][2], qlf[kt][3], al);
            }
        }
        const int kb = kb0 + j;
        const __nv_bfloat16* khs = KV + (j & 1) * 4 * 64 * ALDA;
        const __nv_bfloat16* kls = khs + 64 * ALDA;
        const __nv_bfloat16* vhs = khs + 2 * 64 * ALDA;
        const __nv_bfloat16* vls = khs + 3 * 64 * ALDA;

        float s[8][4];
#pragma unroll
        for (int nt = 0; nt < 8; nt++)
#pragma unroll
            for (int c = 0; c < 4; c++) s[nt][c] = 0.f;

#pragma unroll
        for (int kt = 0; kt < 4; kt++) {
            uint32_t bh[8][2], bl[8][2];
#pragma unroll
            for (int p = 0; p < 4; p++) {
                uint32_t r0, r1, r2, r3;
                uint32_t addr = smem_to_u32(&khs[(p*16 + b_nin) * ALDA + kt*16 + b_ch*8]);
                ldsm4(r0, r1, r2, r3, addr);
                bh[2*p][0] = r0; bh[2*p][1] = r1; bh[2*p+1][0] = r2; bh[2*p+1][1] = r3;
                addr = smem_to_u32(&kls[(p*16 + b_nin) * ALDA + kt*16 + b_ch*8]);
                ldsm4(r0, r1, r2, r3, addr);
                bl[2*p][0] = r0; bl[2*p][1] = r1; bl[2*p+1][0] = r2; bl[2*p+1][1] = r3;
            }
#pragma unroll
            for (int nt = 0; nt < 8; nt++) {
                mma16816(s[nt], qhf[kt][0], qhf[kt][1], qhf[kt][2], qhf[kt][3], bh[nt][0], bh[nt][1]);
                mma16816(s[nt], qhf[kt][0], qhf[kt][1], qhf[kt][2], qhf[kt][3], bl[nt][0], bl[nt][1]);
                mma16816(s[nt], qlf[kt][0], qlf[kt][1], qlf[kt][2], qlf[kt][3], bh[nt][0], bh[nt][1]);
            }
        }

        float mxA = -1e30f, mxB = -1e30f;
#pragma unroll
        for (int nt = 0; nt < 8; nt++) {
            int jb = kb * 64 + nt * 8 + (lane & 3) * 2;
            int d0 = i0 - jb;
            if ((unsigned)d0       > 256u) s[nt][0] = -1e30f;
            if ((unsigned)(d0 - 1) > 256u) s[nt][1] = -1e30f;
            if ((unsigned)(d0 + 8) > 256u) s[nt][2] = -1e30f;
            if ((unsigned)(d0 + 7) > 256u) s[nt][3] = -1e30f;
            mxA = fmaxf(mxA, fmaxf(s[nt][0], s[nt][1]));
            mxB = fmaxf(mxB, fmaxf(s[nt][2], s[nt][3]));
        }
        mxA = fmaxf(mxA, __shfl_xor_sync(0xffffffffu, mxA, 1));
        mxA = fmaxf(mxA, __shfl_xor_sync(0xffffffffu, mxA, 2));
        mxB = fmaxf(mxB, __shfl_xor_sync(0xffffffffu, mxB, 1));
        mxB = fmaxf(mxB, __shfl_xor_sync(0xffffffffu, mxB, 2));
        float nm0 = fmaxf(m0, mxA), nm1 = fmaxf(m1, mxB);
        float al0 = __expf(m0 - nm0), al1 = __expf(m1 - nm1);
        m0 = nm0; m1 = nm1;
        float rs0 = 0.f, rs1 = 0.f;
#pragma unroll
        for (int nt = 0; nt < 8; nt++) {
            s[nt][0] = __expf(s[nt][0] - m0);
            s[nt][1] = __expf(s[nt][1] - m0);
            s[nt][2] = __expf(s[nt][2] - m1);
            s[nt][3] = __expf(s[nt][3] - m1);
            rs0 += s[nt][0] + s[nt][1];
            rs1 += s[nt][2] + s[nt][3];
            o[nt][0] *= al0; o[nt][1] *= al0; o[nt][2] *= al1; o[nt][3] *= al1;
        }
        rs0 += __shfl_xor_sync(0xffffffffu, rs0, 1);
        rs0 += __shfl_xor_sync(0xffffffffu, rs0, 2);
        rs1 += __shfl_xor_sync(0xffffffffu, rs1, 1);
        rs1 += __shfl_xor_sync(0xffffffffu, rs1, 2);
        l0 = l0 * al0 + rs0;
        l1 = l1 * al1 + rs1;

#pragma unroll
        for (int kt = 0; kt < 4; kt++) {
            uint32_t pha[4], pla[4];
            {
                const int t0 = 2 * kt, t1 = 2 * kt + 1;
                __nv_bfloat16 h00 = __float2bfloat16_rn(s[t0][0]);
                __nv_bfloat16 h01 = __float2bfloat16_rn(s[t0][1]);
                __nv_bfloat16 h02 = __float2bfloat16_rn(s[t0][2]);
                __nv_bfloat16 h03 = __float2bfloat16_rn(s[t0][3]);
                __nv_bfloat16 h10 = __float2bfloat16_rn(s[t1][0]);
                __nv_bfloat16 h11 = __float2bfloat16_rn(s[t1][1]);
                __nv_bfloat16 h12 = __float2bfloat16_rn(s[t1][2]);
                __nv_bfloat16 h13 = __float2bfloat16_rn(s[t1][3]);
                pha[0] = ((uint32_t)*(uint16_t*)&h01 << 16) | *(uint16_t*)&h00;
                pha[1] = ((uint32_t)*(uint16_t*)&h03 << 16) | *(uint16_t*)&h02;
                pha[2] = ((uint32_t)*(uint16_t*)&h11 << 16) | *(uint16_t*)&h10;
                pha[3] = ((uint32_t)*(uint16_t*)&h13 << 16) | *(uint16_t*)&h12;
                pla[0] = packbf2(s[t0][0] - __bfloat162float(h00), s[t0][1] - __bfloat162float(h01));
                pla[1] = packbf2(s[t0][2] - __bfloat162float(h02), s[t0][3] - __bfloat162float(h03));
                pla[2] = packbf2(s[t1][0] - __bfloat162float(h10), s[t1][1] - __bfloat162float(h11));
                pla[3] = packbf2(s[t1][2] - __bfloat162float(h12), s[t1][3] - __bfloat162float(h13));
            }
#pragma unroll
            for (int p = 0; p < 4; p++) {
                uint32_t vrow = (kt*16 + ((lane >> 3) & 1)*8 + (lane & 7)) * ALDA + (p*2 + (lane >> 4))*8;
                uint32_t r0, r1, r2, r3, t0, t1, t2, t3;
                ldsm4t(r0, r1, r2, r3, smem_to_u32(&vhs[vrow]));
                ldsm4t(t0, t1, t2, t3, smem_to_u32(&vls[vrow]));
                mma16816(o[2*p],   pha[0], pha[1], pha[2], pha[3], r0, r1);
                mma16816(o[2*p],   pha[0], pha[1], pha[2], pha[3], t0, t1);
                mma16816(o[2*p],   pla[0], pla[1], pla[2], pla[3], r0, r1);
                mma16816(o[2*p+1], pha[0], pha[1], pha[2], pha[3], r2, r3);
                mma16816(o[2*p+1], pha[0], pha[1], pha[2], pha[3], t2, t3);
                mma16816(o[2*p+1], pla[0], pla[1], pla[2], pla[3], r2, r3);
            }
        }

        __syncthreads();
        if (j + 2 < NB) { ALOAD_KV(kb0 + j + 2, j & 1); CP_COMMIT(); }
    }
#undef ALOAD_KV

    const float inv0 = 1.0f / l0, inv1 = 1.0f / l1;
#pragma unroll
    for (int nt = 0; nt < 8; nt++) {
        const int col = nt * 8 + (lane & 3) * 2;
        float v0 = o[nt][0] * inv0, v1 = o[nt][1] * inv0;
        float v2 = o[nt][2] * inv1, v3 = o[nt][3] * inv1;
        __nv_bfloat16 h0 = __float2bfloat16_rn(v0), h1 = __float2bfloat16_rn(v1);
        __nv_bfloat16 h2 = __float2bfloat16_rn(v2), h3 = __float2bfloat16_rn(v3);
        size_t off0 = base + (size_t)i0 * EDIM + col;
        size_t off1 = base + (size_t)(i0 + 8) * EDIM + col;
        *(uint32_t*)(Oh + off0) = ((uint32_t)*(uint16_t*)&h1 << 16) | *(uint16_t*)&h0;
        *(uint32_t*)(Oh + off1) = ((uint32_t)*(uint16_t*)&h3 << 16) | *(uint16_t*)&h2;
        *(uint32_t*)(Ol + off0) = packbf2(v0 - __bfloat162float(h0), v1 - __bfloat162float(h1));
        *(uint32_t*)(Ol + off1) = packbf2(v2 - __bfloat162float(h2), v3 - __bfloat162float(h3));
    }
}

// ---------------- launch ----------------
extern "C" void kernel_launch(void* const* d_in, const int* in_sizes, int n_in,
                              void* d_out, int out_size)
{
    const float* x  = (const float*)d_in[0];
    const float* Wq = (const float*)d_in[1];
    const float* Wk = (const float*)d_in[2];
    const float* Wv = (const float*)d_in[3];
    const float* Wo = (const float*)d_in[4];
    const float* bq = (const float*)d_in[5];
    const float* bk = (const float*)d_in[6];
    const float* bv = (const float*)d_in[7];
    const float* bo = (const float*)d_in[8];

    __nv_bfloat16 *xh, *xl, *qh, *ql, *kh, *kl, *vh, *vl, *yh, *yl, *wh, *wl;
    cudaGetSymbolAddress((void**)&xh, g_xh);
    cudaGetSymbolAddress((void**)&xl, g_xl);
    cudaGetSymbolAddress((void**)&qh, g_qh);
    cudaGetSymbolAddress((void**)&ql, g_ql);
    cudaGetSymbolAddress((void**)&kh, g_kh);
    cudaGetSymbolAddress((void**)&kl, g_kl);
    cudaGetSymbolAddress((void**)&vh, g_vh);
    cudaGetSymbolAddress((void**)&vl, g_vl);
    cudaGetSymbolAddress((void**)&yh, g_yh);
    cudaGetSymbolAddress((void**)&yl, g_yl);
    cudaGetSymbolAddress((void**)&wh, g_wh);
    cudaGetSymbolAddress((void**)&wl, g_wl);

    static bool attr_done = false;
    if (!attr_done) {
        cudaFuncSetAttribute(gemm_tc3,  cudaFuncAttributeMaxDynamicSharedMemorySize, GEMM_SMEM);
        cudaFuncSetAttribute(swattn_tc, cudaFuncAttributeMaxDynamicSharedMemorySize, ATT_SMEM);
        attr_done = true;
    }

    const int NX4 = MROWS * EDIM / 4;   // 1,048,576
    const int NW4 = EDIM * EDIM / 4;    //   262,144
    const size_t WSZ = (size_t)EDIM * EDIM;

    split5<<<dim3((NX4 + 255) / 256, 5), 256>>>(
        x, Wq, Wk, Wv, Wo,
        xh, xl, wh + 0*WSZ, wl + 0*WSZ, wh + 1*WSZ, wl + 1*WSZ,
        wh + 2*WSZ, wl + 2*WSZ, wh + 3*WSZ, wl + 3*WSZ, NX4, NW4);

    // fused QKV projection -> bf16 hi/lo outputs (q pre-scaled by 1/8)
    gemm_tc3<<<dim3(EDIM/BN, MROWS/BM, 3), 256, GEMM_SMEM>>>(
        xh, xl, wh, wl, bq, bk, bv, nullptr,
        qh, ql, kh, kl, vh, vl, 0.125f, 1);

    swattn_tc<<<dim3(SEQ/64, HEADS, BATCH), 128, ATT_SMEM>>>(
        qh, ql, kh, kl, vh, vl, yh, yl);

    // output projection -> fp32 d_out
    gemm_tc3<<<dim3(EDIM/BN, MROWS/BM, 1), 256, GEMM_SMEM>>>(
        yh, yl, wh + 3*WSZ, wl + 3*WSZ, bo, nullptr, nullptr,
        (float*)d_out, nullptr, nullptr, nullptr, nullptr, nullptr, nullptr, 1.0f, 0);
}

// round 12
// speedup vs baseline: 1.3465x; 1.3465x over previous
#include <cuda_runtime.h>
#include <cuda_bf16.h>
#include <cuda_fp16.h>
#include <cstdint>

#define EDIM  1024
#define HEADS 16
#define HD    64
#define WIN   256
#define BATCH 2
#define SEQ   2048
#define MROWS (BATCH*SEQ)   // 4096

// ---------------- scratch (allocation-free rule: device globals) ----------------
static __device__ __half g_xh[MROWS*EDIM];
static __device__ __half g_xl[MROWS*EDIM];
static __device__ __half g_yh[MROWS*EDIM];
static __device__ __half g_yl[MROWS*EDIM];
static __device__ __half g_wf[4][EDIM*EDIM];
static __device__ __nv_bfloat16 g_qh[MROWS*EDIM];
static __device__ __nv_bfloat16 g_ql[MROWS*EDIM];
static __device__ __nv_bfloat16 g_kh[MROWS*EDIM];
static __device__ __nv_bfloat16 g_kl[MROWS*EDIM];
static __device__ __nv_bfloat16 g_vh[MROWS*EDIM];
static __device__ __nv_bfloat16 g_vl[MROWS*EDIM];

// ---------------- family-common PTX helpers ----------------
__device__ __forceinline__ uint32_t smem_to_u32(const void* p) {
    uint32_t a;
    asm("{ .reg .u64 t; cvta.to.shared.u64 t, %1; cvt.u32.u64 %0, t; }"
        : "=r"(a) : "l"(p));
    return a;
}
__device__ __forceinline__ void cp_async16(uint32_t dst, const void* src) {
    asm volatile("cp.async.cg.shared.global [%0], [%1], 16;" :: "r"(dst), "l"(src));
}
#define CP_COMMIT() asm volatile("cp.async.commit_group;" ::: "memory")
#define CP_WAIT1()  asm volatile("cp.async.wait_group 1;" ::: "memory")
#define CP_WAIT0()  asm volatile("cp.async.wait_group 0;" ::: "memory")

__device__ __forceinline__ void ldsm4(uint32_t& r0, uint32_t& r1, uint32_t& r2,
                                      uint32_t& r3, uint32_t addr) {
    asm volatile("ldmatrix.sync.aligned.m8n8.x4.shared.b16 {%0,%1,%2,%3}, [%4];"
                 : "=r"(r0), "=r"(r1), "=r"(r2), "=r"(r3) : "r"(addr));
}
__device__ __forceinline__ void ldsm4t(uint32_t& r0, uint32_t& r1, uint32_t& r2,
                                       uint32_t& r3, uint32_t addr) {
    asm volatile("ldmatrix.sync.aligned.m8n8.x4.trans.shared.b16 {%0,%1,%2,%3}, [%4];"
                 : "=r"(r0), "=r"(r1), "=r"(r2), "=r"(r3) : "r"(addr));
}
// bf16 mma (attention)
__device__ __forceinline__ void mma16816(float* c, uint32_t a0, uint32_t a1,
                                         uint32_t a2, uint32_t a3,
                                         uint32_t b0, uint32_t b1) {
    asm volatile(
        "mma.sync.aligned.m16n8k16.row.col.f32.bf16.bf16.f32 "
        "{%0,%1,%2,%3}, {%4,%5,%6,%7}, {%8,%9}, {%0,%1,%2,%3};"
        : "+f"(c[0]), "+f"(c[1]), "+f"(c[2]), "+f"(c[3])
        : "r"(a0), "r"(a1), "r"(a2), "r"(a3), "r"(b0), "r"(b1));
}
// fp16 mma (projection GEMMs)
__device__ __forceinline__ void mma16816h(float* c, uint32_t a0, uint32_t a1,
                                          uint32_t a2, uint32_t a3,
                                          uint32_t b0, uint32_t b1) {
    asm volatile(
        "mma.sync.aligned.m16n8k16.row.col.f32.f16.f16.f32 "
        "{%0,%1,%2,%3}, {%4,%5,%6,%7}, {%8,%9}, {%0,%1,%2,%3};"
        : "+f"(c[0]), "+f"(c[1]), "+f"(c[2]), "+f"(c[3])
        : "r"(a0), "r"(a1), "r"(a2), "r"(a3), "r"(b0), "r"(b1));
}
__device__ __forceinline__ uint32_t packbf2(float a, float b) {
    __nv_bfloat162 t = __floats2bfloat162_rn(a, b);
    return *(uint32_t*)&t;
}
__device__ __forceinline__ uint32_t packh2(float a, float b) {
    __half2 t = __floats2half2_rn(a, b);
    return *(uint32_t*)&t;
}

// ---------------- fused fp32 -> fp16 convert (x: hi/lo split, W: single) -------
__global__ __launch_bounds__(256)
void split5(const float* __restrict__ s0, const float* __restrict__ s1,
            const float* __restrict__ s2, const float* __restrict__ s3,
            const float* __restrict__ s4,
            __half* __restrict__ xh, __half* __restrict__ xl,
            __half* __restrict__ wf,   // 4 slabs of EDIM*EDIM
            int n0, int nw)
{
    const int t = blockIdx.y;
    const int n4 = (t == 0) ? n0 : nw;
    int i = blockIdx.x * 256 + threadIdx.x;
    if (i >= n4) return;
    const float* in = (t == 0) ? s0 : (t == 1) ? s1 : (t == 2) ? s2 : (t == 3) ? s3 : s4;
    float4 v = ((const float4*)in)[i];
    float vv[4] = {v.x, v.y, v.z, v.w};
    __half h[4];
#pragma unroll
    for (int j = 0; j < 4; j++) h[j] = __float2half_rn(vv[j]);
    if (t == 0) {
        __half l[4];
#pragma unroll
        for (int j = 0; j < 4; j++) l[j] = __float2half_rn(vv[j] - __half2float(h[j]));
        ((uint2*)xh)[i] = *(uint2*)h;
        ((uint2*)xl)[i] = *(uint2*)l;
    } else {
        __half* dst = wf + (size_t)(t - 1) * EDIM * EDIM;
        ((uint2*)dst)[i] = *(uint2*)h;
    }
}

// ---------------- fp16 warp-MMA GEMM, 2-pass (A=hi+lo fp16, W=fp16) ----------------
// C[256x128 per CTA] = scale * ((Ah+Al)@Wf^T + bias)
// 8 warps each 64x64. BKC=64, 2 smem stages.
#define BM   256
#define BN   128
#define BKC  64
#define LDSB 72
#define A2OFF (256*LDSB)
#define WFOFF (512*LDSB)
#define STAGE (640*LDSB)                 // elements per stage
#define GEMM_SMEM (2*STAGE*2)            // 184,320 B -> 1 CTA/SM, 8 warps

__global__ __launch_bounds__(256, 1)
void gemm_tc2(const __half* __restrict__ Ah, const __half* __restrict__ Al,
              const __half* __restrict__ Wf,
              const float* __restrict__ b0v, const float* __restrict__ b1v,
              const float* __restrict__ b2v,
              float* __restrict__ Cf,
              __nv_bfloat16* __restrict__ H0, __nv_bfloat16* __restrict__ L0,
              __nv_bfloat16* __restrict__ H1, __nv_bfloat16* __restrict__ L1,
              __nv_bfloat16* __restrict__ H2, __nv_bfloat16* __restrict__ L2,
              float s0, int bf16out)
{
    extern __shared__ __align__(16) __half gsm[];

    const int tid  = threadIdx.x;
    const int wid  = tid >> 5;
    const int lane = tid & 31;
    const int bm   = blockIdx.y * BM;
    const int bn   = blockIdx.x * BN;
    const int z    = blockIdx.z;
    const int wm   = (wid & 3) * 64;
    const int wn   = (wid >> 2) * 64;

    const __half* Wfb = Wf + (size_t)z * EDIM * EDIM + (size_t)bn * EDIM;
    const __half* Ahb = Ah + (size_t)bm * EDIM;
    const __half* Alb = Al + (size_t)bm * EDIM;
    const float* bias = (z == 0) ? b0v : (z == 1) ? b1v : b2v;
    const float scale = (z == 0) ? s0 : 1.0f;

    float acc[4][8][4];
#pragma unroll
    for (int mt = 0; mt < 4; mt++)
#pragma unroll
        for (int nt = 0; nt < 8; nt++)
#pragma unroll
            for (int j = 0; j < 4; j++) acc[mt][nt][j] = 0.f;

    const int a_row = lane & 15, a_ch = lane >> 4;
    const int b_nin = (lane & 7) + ((lane >= 16) ? 8 : 0);
    const int b_ch  = (lane >> 3) & 1;

// one chunk: Ah,Al 256x64 (8 segs/thread each), Wf 128x64 (4 segs/thread)
#define LOADC(cc, st) do { \
    const int _kc = (cc); \
    __half* _sa = gsm + (st) * STAGE; \
    const __half* _ah = Ahb + (size_t)_kc * BKC; \
    const __half* _al = Alb + (size_t)_kc * BKC; \
    const __half* _wf = Wfb + (size_t)_kc * BKC; \
    _Pragma("unroll") \
    for (int _i = 0; _i < 8; _i++) { \
        int _idx = tid + _i * 256; int _r = _idx >> 3, _s = _idx & 7; \
        cp_async16(smem_to_u32(&_sa[_r * LDSB + _s * 8]), _ah + (size_t)_r * EDIM + _s * 8); \
        cp_async16(smem_to_u32(&_sa[A2OFF + _r * LDSB + _s * 8]), _al + (size_t)_r * EDIM + _s * 8); \
    } \
    _Pragma("unroll") \
    for (int _i = 0; _i < 4; _i++) { \
        int _idx = tid + _i * 256; int _r = _idx >> 3, _s = _idx & 7; \
        cp_async16(smem_to_u32(&_sa[WFOFF + _r * LDSB + _s * 8]), _wf + (size_t)_r * EDIM + _s * 8); \
    } \
} while (0)

    const int NCH = EDIM / BKC;          // 16
    LOADC(0, 0); CP_COMMIT();

    for (int c = 0; c < NCH; c++) {
        CP_WAIT0();
        __syncthreads();
        if (c + 1 < NCH) { LOADC(c + 1, (c + 1) & 1); CP_COMMIT(); }

        const __half* st = gsm + (c & 1) * STAGE;
#pragma unroll
        for (int ks = 0; ks < 4; ks++) {
            const int k0 = ks * 16;
            uint32_t wf2[8][2];
#pragma unroll
            for (int p = 0; p < 4; p++) {
                uint32_t base = (wn + p * 16 + b_nin) * LDSB + k0 + b_ch * 8;
                uint32_t r0, r1, r2, r3;
                ldsm4(r0, r1, r2, r3, smem_to_u32(&st[WFOFF + base]));
                wf2[2*p][0] = r0; wf2[2*p][1] = r1; wf2[2*p+1][0] = r2; wf2[2*p+1][1] = r3;
            }
#pragma unroll
            for (int mt = 0; mt < 4; mt++) {
                uint32_t ahf[4], alf[4];
                uint32_t base = (wm + mt * 16 + a_row) * LDSB + k0 + a_ch * 8;
                ldsm4(ahf[0], ahf[1], ahf[2], ahf[3], smem_to_u32(&st[base]));
                ldsm4(alf[0], alf[1], alf[2], alf[3], smem_to_u32(&st[A2OFF + base]));
#pragma unroll
                for (int nt = 0; nt < 8; nt++)
                    mma16816h(acc[mt][nt], ahf[0], ahf[1], ahf[2], ahf[3],
                              wf2[nt][0], wf2[nt][1]);
#pragma unroll
                for (int nt = 0; nt < 8; nt++)
                    mma16816h(acc[mt][nt], alf[0], alf[1], alf[2], alf[3],
                              wf2[nt][0], wf2[nt][1]);
            }
        }
    }
#undef LOADC

    if (bf16out) {
        __nv_bfloat16* H = (z == 0) ? H0 : (z == 1) ? H1 : H2;
        __nv_bfloat16* L = (z == 0) ? L0 : (z == 1) ? L1 : L2;
#pragma unroll
        for (int nt = 0; nt < 8; nt++) {
            const int col = bn + wn + nt * 8 + (lane & 3) * 2;
            const float c0 = bias[col], c1 = bias[col + 1];
#pragma unroll
            for (int mt = 0; mt < 4; mt++) {
                const int r0 = bm + wm + mt * 16 + (lane >> 2);
#pragma unroll
                for (int rr = 0; rr < 2; rr++) {
                    float vx = (acc[mt][nt][2*rr+0] + c0) * scale;
                    float vy = (acc[mt][nt][2*rr+1] + c1) * scale;
                    __nv_bfloat16 hx = __float2bfloat16_rn(vx);
                    __nv_bfloat16 hy = __float2bfloat16_rn(vy);
                    float lx = vx - __bfloat162float(hx);
                    float ly = vy - __bfloat162float(hy);
                    size_t off = (size_t)(r0 + rr*8) * EDIM + col;
                    *(uint32_t*)(H + off) = ((uint32_t)*(uint16_t*)&hy << 16) | *(uint16_t*)&hx;
                    *(uint32_t*)(L + off) = packbf2(lx, ly);
                }
            }
        }
    } else {
#pragma unroll
        for (int nt = 0; nt < 8; nt++) {
            const int col = bn + wn + nt * 8 + (lane & 3) * 2;
            const float c0 = bias[col], c1 = bias[col + 1];
#pragma unroll
            for (int mt = 0; mt < 4; mt++) {
                const int r0 = bm + wm + mt * 16 + (lane >> 2);
                *(float2*)&Cf[(size_t)r0 * EDIM + col] =
                    make_float2((acc[mt][nt][0] + c0) * scale, (acc[mt][nt][1] + c1) * scale);
                *(float2*)&Cf[(size_t)(r0 + 8) * EDIM + col] =
                    make_float2((acc[mt][nt][2] + c0) * scale, (acc[mt][nt][3] + c1) * scale);
            }
        }
    }
}

// ---------------- sliding-window flash attention, bf16-split warp MMA ----------------
// (internals unchanged from proven R10 version; epilogue now emits fp16 hi/lo)
#define ALDA 72
#define ATT_SMEM ((2*64 + 2*4*64) * ALDA * 2)   // 92160 B

__global__ __launch_bounds__(128)
void swattn_tc(const __nv_bfloat16* __restrict__ Qh, const __nv_bfloat16* __restrict__ Ql,
               const __nv_bfloat16* __restrict__ Kh, const __nv_bfloat16* __restrict__ Kl,
               const __nv_bfloat16* __restrict__ Vh, const __nv_bfloat16* __restrict__ Vl,
               __half* __restrict__ Oh, __half* __restrict__ Ol)
{
    extern __shared__ __align__(16) __nv_bfloat16 sb[];
    __nv_bfloat16* Qsh = sb;
    __nv_bfloat16* Qsl = Qsh + 64 * ALDA;
    __nv_bfloat16* KV  = Qsl + 64 * ALDA;     // [buf][4][64*ALDA]

    const int tid = threadIdx.x, wid = tid >> 5, lane = tid & 31;
    const int qt = blockIdx.x, h = blockIdx.y, b = blockIdx.z;
    const int q0 = qt * 64;
    const size_t base = (size_t)b * SEQ * EDIM + (size_t)h * HD;
    const int kb0 = (qt > 4) ? qt - 4 : 0;
    const int NB  = qt - kb0 + 1;

    {
        const __nv_bfloat16* qs[2] = {Qh, Ql};
        __nv_bfloat16* qd[2] = {Qsh, Qsl};
#pragma unroll
        for (int i = 0; i < 8; i++) {
            int idx = tid + i * 128;
            int t = idx >> 9, r = (idx >> 3) & 63, s = idx & 7;
            cp_async16(smem_to_u32(qd[t] + r * ALDA + s * 8),
                       qs[t] + base + (size_t)(q0 + r) * EDIM + s * 8);
        }
    }
    CP_COMMIT();

#define ALOAD_KV(kb, buf) do { \
    const __nv_bfloat16* _srcs[4] = {Kh, Kl, Vh, Vl}; \
    __nv_bfloat16* _d = KV + (buf) * 4 * 64 * ALDA; \
    _Pragma("unroll") \
    for (int _i = 0; _i < 16; _i++) { \
        int _idx = tid + _i * 128; \
        int _t = _idx >> 9, _r = (_idx >> 3) & 63, _s = _idx & 7; \
        cp_async16(smem_to_u32(_d + _t * 64 * ALDA + _r * ALDA + _s * 8), \
                   _srcs[_t] + base + (size_t)((kb) * 64 + _r) * EDIM + _s * 8); \
    } \
} while (0)

    ALOAD_KV(kb0, 0); CP_COMMIT();
    if (NB >= 2) { ALOAD_KV(kb0 + 1, 1); CP_COMMIT(); }

    const int b_nin = (lane & 7) + ((lane >= 16) ? 8 : 0);
    const int b_ch  = (lane >> 3) & 1;

    uint32_t qhf[4][4], qlf[4][4];
    float o[8][4];
#pragma unroll
    for (int nt = 0; nt < 8; nt++)
#pragma unroll
        for (int j = 0; j < 4; j++) o[nt][j] = 0.f;
    float m0 = -1e30f, m1 = -1e30f, l0 = 0.f, l1 = 0.f;
    const int i0 = q0 + wid * 16 + (lane >> 2);

    for (int j = 0; j < NB; j++) {
        if (j + 1 < NB) CP_WAIT1(); else CP_WAIT0();
        __syncthreads();
        if (j == 0) {
#pragma unroll
            for (int kt = 0; kt < 4; kt++) {
                uint32_t ah = smem_to_u32(&Qsh[(wid*16 + (lane & 15)) * ALDA + kt*16 + (lane >> 4)*8]);
                uint32_t al = smem_to_u32(&Qsl[(wid*16 + (lane & 15)) * ALDA + kt*16 + (lane >> 4)*8]);
                ldsm4(qhf[kt][0], qhf[kt][1], qhf[kt][2], qhf[kt][3], ah);
                ldsm4(qlf[kt][0], qlf[kt][1], qlf[kt][2], qlf[kt][3], al);
            }
        }
        const int kb = kb0 + j;
        const __nv_bfloat16* khs = KV + (j & 1) * 4 * 64 * ALDA;
        const __nv_bfloat16* kls = khs + 64 * ALDA;
        const __nv_bfloat16* vhs = khs + 2 * 64 * ALDA;
        const __nv_bfloat16* vls = khs + 3 * 64 * ALDA;

        float s[8][4];
#pragma unroll
        for (int nt = 0; nt < 8; nt++)
#pragma unroll
            for (int c = 0; c < 4; c++) s[nt][c] = 0.f;

#pragma unroll
        for (int kt = 0; kt < 4; kt++) {
            uint32_t bh[8][2], bl[8][2];
#pragma unroll
            for (int p = 0; p < 4; p++) {
                uint32_t r0, r1, r2, r3;
                uint32_t addr = smem_to_u32(&khs[(p*16 + b_nin) * ALDA + kt*16 + b_ch*8]);
                ldsm4(r0, r1, r2, r3, addr);
                bh[2*p][0] = r0; bh[2*p][1] = r1; bh[2*p+1][0] = r2; bh[2*p+1][1] = r3;
                addr = smem_to_u32(&kls[(p*16 + b_nin) * ALDA + kt*16 + b_ch*8]);
                ldsm4(r0, r1, r2, r3, addr);
                bl[2*p][0] = r0; bl[2*p][1] = r1; bl[2*p+1][0] = r2; bl[2*p+1][1] = r3;
            }
#pragma unroll
            for (int nt = 0; nt < 8; nt++) {
                mma16816(s[nt], qhf[kt][0], qhf[kt][1], qhf[kt][2], qhf[kt][3], bh[nt][0], bh[nt][1]);
                mma16816(s[nt], qhf[kt][0], qhf[kt][1], qhf[kt][2], qhf[kt][3], bl[nt][0], bl[nt][1]);
                mma16816(s[nt], qlf[kt][0], qlf[kt][1], qlf[kt][2], qlf[kt][3], bh[nt][0], bh[nt][1]);
            }
        }

        float mxA = -1e30f, mxB = -1e30f;
#pragma unroll
        for (int nt = 0; nt < 8; nt++) {
            int jb = kb * 64 + nt * 8 + (lane & 3) * 2;
            int d0 = i0 - jb;
            if ((unsigned)d0       > 256u) s[nt][0] = -1e30f;
            if ((unsigned)(d0 - 1) > 256u) s[nt][1] = -1e30f;
            if ((unsigned)(d0 + 8) > 256u) s[nt][2] = -1e30f;
            if ((unsigned)(d0 + 7) > 256u) s[nt][3] = -1e30f;
            mxA = fmaxf(mxA, fmaxf(s[nt][0], s[nt][1]));
            mxB = fmaxf(mxB, fmaxf(s[nt][2], s[nt][3]));
        }
        mxA = fmaxf(mxA, __shfl_xor_sync(0xffffffffu, mxA, 1));
        mxA = fmaxf(mxA, __shfl_xor_sync(0xffffffffu, mxA, 2));
        mxB = fmaxf(mxB, __shfl_xor_sync(0xffffffffu, mxB, 1));
        mxB = fmaxf(mxB, __shfl_xor_sync(0xffffffffu, mxB, 2));
        float nm0 = fmaxf(m0, mxA), nm1 = fmaxf(m1, mxB);
        float al0 = __expf(m0 - nm0), al1 = __expf(m1 - nm1);
        m0 = nm0; m1 = nm1;
        float rs0 = 0.f, rs1 = 0.f;
#pragma unroll
        for (int nt = 0; nt < 8; nt++) {
            s[nt][0] = __expf(s[nt][0] - m0);
            s[nt][1] = __expf(s[nt][1] - m0);
            s[nt][2] = __expf(s[nt][2] - m1);
            s[nt][3] = __expf(s[nt][3] - m1);
            rs0 += s[nt][0] + s[nt][1];
            rs1 += s[nt][2] + s[nt][3];
            o[nt][0] *= al0; o[nt][1] *= al0; o[nt][2] *= al1; o[nt][3] *= al1;
        }
        rs0 += __shfl_xor_sync(0xffffffffu, rs0, 1);
        rs0 += __shfl_xor_sync(0xffffffffu, rs0, 2);
        rs1 += __shfl_xor_sync(0xffffffffu, rs1, 1);
        rs1 += __shfl_xor_sync(0xffffffffu, rs1, 2);
        l0 = l0 * al0 + rs0;
        l1 = l1 * al1 + rs1;

#pragma unroll
        for (int kt = 0; kt < 4; kt++) {
            uint32_t pha[4], pla[4];
            {
                const int t0 = 2 * kt, t1 = 2 * kt + 1;
                __nv_bfloat16 h00 = __float2bfloat16_rn(s[t0][0]);
                __nv_bfloat16 h01 = __float2bfloat16_rn(s[t0][1]);
                __nv_bfloat16 h02 = __float2bfloat16_rn(s[t0][2]);
                __nv_bfloat16 h03 = __float2bfloat16_rn(s[t0][3]);
                __nv_bfloat16 h10 = __float2bfloat16_rn(s[t1][0]);
                __nv_bfloat16 h11 = __float2bfloat16_rn(s[t1][1]);
                __nv_bfloat16 h12 = __float2bfloat16_rn(s[t1][2]);
                __nv_bfloat16 h13 = __float2bfloat16_rn(s[t1][3]);
                pha[0] = ((uint32_t)*(uint16_t*)&h01 << 16) | *(uint16_t*)&h00;
                pha[1] = ((uint32_t)*(uint16_t*)&h03 << 16) | *(uint16_t*)&h02;
                pha[2] = ((uint32_t)*(uint16_t*)&h11 << 16) | *(uint16_t*)&h10;
                pha[3] = ((uint32_t)*(uint16_t*)&h13 << 16) | *(uint16_t*)&h12;
                pla[0] = packbf2(s[t0][0] - __bfloat162float(h00), s[t0][1] - __bfloat162float(h01));
                pla[1] = packbf2(s[t0][2] - __bfloat162float(h02), s[t0][3] - __bfloat162float(h03));
                pla[2] = packbf2(s[t1][0] - __bfloat162float(h10), s[t1][1] - __bfloat162float(h11));
                pla[3] = packbf2(s[t1][2] - __bfloat162float(h12), s[t1][3] - __bfloat162float(h13));
            }
#pragma unroll
            for (int p = 0; p < 4; p++) {
                uint32_t vrow = (kt*16 + ((lane >> 3) & 1)*8 + (lane & 7)) * ALDA + (p*2 + (lane >> 4))*8;
                uint32_t r0, r1, r2, r3, t0, t1, t2, t3;
                ldsm4t(r0, r1, r2, r3, smem_to_u32(&vhs[vrow]));
                ldsm4t(t0, t1, t2, t3, smem_to_u32(&vls[vrow]));
                mma16816(o[2*p],   pha[0], pha[1], pha[2], pha[3], r0, r1);
                mma16816(o[2*p],   pha[0], pha[1], pha[2], pha[3], t0, t1);
                mma16816(o[2*p],   pla[0], pla[1], pla[2], pla[3], r0, r1);
                mma16816(o[2*p+1], pha[0], pha[1], pha[2], pha[3], r2, r3);
                mma16816(o[2*p+1], pha[0], pha[1], pha[2], pha[3], t2, t3);
                mma16816(o[2*p+1], pla[0], pla[1], pla[2], pla[3], r2, r3);
            }
        }

        __syncthreads();
        if (j + 2 < NB) { ALOAD_KV(kb0 + j + 2, j & 1); CP_COMMIT(); }
    }
#undef ALOAD_KV

    // epilogue: write fp16 hi/lo for the Wo GEMM
    const float inv0 = 1.0f / l0, inv1 = 1.0f / l1;
#pragma unroll
    for (int nt = 0; nt < 8; nt++) {
        const int col = nt * 8 + (lane & 3) * 2;
        float v0 = o[nt][0] * inv0, v1 = o[nt][1] * inv0;
        float v2 = o[nt][2] * inv1, v3 = o[nt][3] * inv1;
        __half h0 = __float2half_rn(v0), h1 = __float2half_rn(v1);
        __half h2 = __float2half_rn(v2), h3 = __float2half_rn(v3);
        size_t off0 = base + (size_t)i0 * EDIM + col;
        size_t off1 = base + (size_t)(i0 + 8) * EDIM + col;
        *(uint32_t*)(Oh + off0) = ((uint32_t)*(uint16_t*)&h1 << 16) | *(uint16_t*)&h0;
        *(uint32_t*)(Oh + off1) = ((uint32_t)*(uint16_t*)&h3 << 16) | *(uint16_t*)&h2;
        *(uint32_t*)(Ol + off0) = packh2(v0 - __half2float(h0), v1 - __half2float(h1));
        *(uint32_t*)(Ol + off1) = packh2(v2 - __half2float(h2), v3 - __half2float(h3));
    }
}

// ---------------- launch ----------------
extern "C" void kernel_launch(void* const* d_in, const int* in_sizes, int n_in,
                              void* d_out, int out_size)
{
    const float* x  = (const float*)d_in[0];
    const float* Wq = (const float*)d_in[1];
    const float* Wk = (const float*)d_in[2];
    const float* Wv = (const float*)d_in[3];
    const float* Wo = (const float*)d_in[4];
    const float* bq = (const float*)d_in[5];
    const float* bk = (const float*)d_in[6];
    const float* bv = (const float*)d_in[7];
    const float* bo = (const float*)d_in[8];

    __half *xh, *xl, *yh, *yl, *wf;
    __nv_bfloat16 *qh, *ql, *kh, *kl, *vh, *vl;
    cudaGetSymbolAddress((void**)&xh, g_xh);
    cudaGetSymbolAddress((void**)&xl, g_xl);
    cudaGetSymbolAddress((void**)&yh, g_yh);
    cudaGetSymbolAddress((void**)&yl, g_yl);
    cudaGetSymbolAddress((void**)&wf, g_wf);
    cudaGetSymbolAddress((void**)&qh, g_qh);
    cudaGetSymbolAddress((void**)&ql, g_ql);
    cudaGetSymbolAddress((void**)&kh, g_kh);
    cudaGetSymbolAddress((void**)&kl, g_kl);
    cudaGetSymbolAddress((void**)&vh, g_vh);
    cudaGetSymbolAddress((void**)&vl, g_vl);

    static bool attr_done = false;
    if (!attr_done) {
        cudaFuncSetAttribute(gemm_tc2,  cudaFuncAttributeMaxDynamicSharedMemorySize, GEMM_SMEM);
        cudaFuncSetAttribute(swattn_tc, cudaFuncAttributeMaxDynamicSharedMemorySize, ATT_SMEM);
        attr_done = true;
    }

    const int NX4 = MROWS * EDIM / 4;   // 1,048,576
    const int NW4 = EDIM * EDIM / 4;    //   262,144
    const size_t WSZ = (size_t)EDIM * EDIM;

    split5<<<dim3((NX4 + 255) / 256, 5), 256>>>(
        x, Wq, Wk, Wv, Wo, xh, xl, wf, NX4, NW4);

    // fused QKV projection -> bf16 hi/lo outputs (q pre-scaled by 1/8)
    gemm_tc2<<<dim3(EDIM/BN, MROWS/BM, 3), 256, GEMM_SMEM>>>(
        xh, xl, wf, bq, bk, bv, nullptr,
        qh, ql, kh, kl, vh, vl, 0.125f, 1);

    swattn_tc<<<dim3(SEQ/64, HEADS, BATCH), 128, ATT_SMEM>>>(
        qh, ql, kh, kl, vh, vl, yh, yl);

    // output projection -> fp32 d_out
    gemm_tc2<<<dim3(EDIM/BN, MROWS/BM, 1), 256, GEMM_SMEM>>>(
        yh, yl, wf + 3*WSZ, bo, nullptr, nullptr,
        (float*)d_out, nullptr, nullptr, nullptr, nullptr, nullptr, nullptr, 1.0f, 0);
}

// round 13
// speedup vs baseline: 1.5782x; 1.1721x over previous
#include <cuda_runtime.h>
#include <cuda_bf16.h>
#include <cuda_fp16.h>
#include <cstdint>

#define EDIM  1024
#define HEADS 16
#define HD    64
#define WIN   256
#define BATCH 2
#define SEQ   2048
#define MROWS (BATCH*SEQ)   // 4096

// ---------------- scratch (allocation-free rule: device globals) ----------------
static __device__ __half g_xh[MROWS*EDIM];
static __device__ __half g_xl[MROWS*EDIM];
static __device__ __half g_qf[MROWS*EDIM];
static __device__ __half g_kf[MROWS*EDIM];
static __device__ __half g_vf[MROWS*EDIM];
static __device__ __half g_yh[MROWS*EDIM];
static __device__ __half g_yl[MROWS*EDIM];
static __device__ __half g_wf[4][EDIM*EDIM];

// ---------------- family-common PTX helpers ----------------
__device__ __forceinline__ uint32_t smem_to_u32(const void* p) {
    uint32_t a;
    asm("{ .reg .u64 t; cvta.to.shared.u64 t, %1; cvt.u32.u64 %0, t; }"
        : "=r"(a) : "l"(p));
    return a;
}
__device__ __forceinline__ void cp_async16(uint32_t dst, const void* src) {
    asm volatile("cp.async.cg.shared.global [%0], [%1], 16;" :: "r"(dst), "l"(src));
}
#define CP_COMMIT() asm volatile("cp.async.commit_group;" ::: "memory")
#define CP_WAIT1()  asm volatile("cp.async.wait_group 1;" ::: "memory")
#define CP_WAIT0()  asm volatile("cp.async.wait_group 0;" ::: "memory")

__device__ __forceinline__ void ldsm4(uint32_t& r0, uint32_t& r1, uint32_t& r2,
                                      uint32_t& r3, uint32_t addr) {
    asm volatile("ldmatrix.sync.aligned.m8n8.x4.shared.b16 {%0,%1,%2,%3}, [%4];"
                 : "=r"(r0), "=r"(r1), "=r"(r2), "=r"(r3) : "r"(addr));
}
__device__ __forceinline__ void ldsm4t(uint32_t& r0, uint32_t& r1, uint32_t& r2,
                                       uint32_t& r3, uint32_t addr) {
    asm volatile("ldmatrix.sync.aligned.m8n8.x4.trans.shared.b16 {%0,%1,%2,%3}, [%4];"
                 : "=r"(r0), "=r"(r1), "=r"(r2), "=r"(r3) : "r"(addr));
}
// fp16 mma
__device__ __forceinline__ void mma16816h(float* c, uint32_t a0, uint32_t a1,
                                          uint32_t a2, uint32_t a3,
                                          uint32_t b0, uint32_t b1) {
    asm volatile(
        "mma.sync.aligned.m16n8k16.row.col.f32.f16.f16.f32 "
        "{%0,%1,%2,%3}, {%4,%5,%6,%7}, {%8,%9}, {%0,%1,%2,%3};"
        : "+f"(c[0]), "+f"(c[1]), "+f"(c[2]), "+f"(c[3])
        : "r"(a0), "r"(a1), "r"(a2), "r"(a3), "r"(b0), "r"(b1));
}
__device__ __forceinline__ uint32_t packh2(float a, float b) {
    __half2 t = __floats2half2_rn(a, b);
    return *(uint32_t*)&t;
}

// ---------------- fused fp32 -> fp16 convert (x: hi/lo split, W: single) -------
__global__ __launch_bounds__(256)
void split5(const float* __restrict__ s0, const float* __restrict__ s1,
            const float* __restrict__ s2, const float* __restrict__ s3,
            const float* __restrict__ s4,
            __half* __restrict__ xh, __half* __restrict__ xl,
            __half* __restrict__ wf, int n0, int nw)
{
    const int t = blockIdx.y;
    const int n4 = (t == 0) ? n0 : nw;
    int i = blockIdx.x * 256 + threadIdx.x;
    if (i >= n4) return;
    const float* in = (t == 0) ? s0 : (t == 1) ? s1 : (t == 2) ? s2 : (t == 3) ? s3 : s4;
    float4 v = ((const float4*)in)[i];
    float vv[4] = {v.x, v.y, v.z, v.w};
    __half h[4];
#pragma unroll
    for (int j = 0; j < 4; j++) h[j] = __float2half_rn(vv[j]);
    if (t == 0) {
        __half l[4];
#pragma unroll
        for (int j = 0; j < 4; j++) l[j] = __float2half_rn(vv[j] - __half2float(h[j]));
        ((uint2*)xh)[i] = *(uint2*)h;
        ((uint2*)xl)[i] = *(uint2*)l;
    } else {
        __half* dst = wf + (size_t)(t - 1) * EDIM * EDIM;
        ((uint2*)dst)[i] = *(uint2*)h;
    }
}

// ---------------- fp16 warp-MMA GEMM, 2-pass (A=hi+lo fp16, W=fp16) ----------------
#define BM   256
#define BN   128
#define BKC  64
#define LDSB 72
#define A2OFF (256*LDSB)
#define WFOFF (512*LDSB)
#define STAGE (640*LDSB)
#define GEMM_SMEM (2*STAGE*2)            // 184,320 B -> 1 CTA/SM, 8 warps

__global__ __launch_bounds__(256, 1)
void gemm_tc2(const __half* __restrict__ Ah, const __half* __restrict__ Al,
              const __half* __restrict__ Wf,
              const float* __restrict__ b0v, const float* __restrict__ b1v,
              const float* __restrict__ b2v,
              float* __restrict__ Cf,
              __half* __restrict__ O0, __half* __restrict__ O1, __half* __restrict__ O2,
              float s0, int fp16out)
{
    extern __shared__ __align__(16) __half gsm[];

    const int tid  = threadIdx.x;
    const int wid  = tid >> 5;
    const int lane = tid & 31;
    const int bm   = blockIdx.y * BM;
    const int bn   = blockIdx.x * BN;
    const int z    = blockIdx.z;
    const int wm   = (wid & 3) * 64;
    const int wn   = (wid >> 2) * 64;

    const __half* Wfb = Wf + (size_t)z * EDIM * EDIM + (size_t)bn * EDIM;
    const __half* Ahb = Ah + (size_t)bm * EDIM;
    const __half* Alb = Al + (size_t)bm * EDIM;
    const float* bias = (z == 0) ? b0v : (z == 1) ? b1v : b2v;
    const float scale = (z == 0) ? s0 : 1.0f;

    float acc[4][8][4];
#pragma unroll
    for (int mt = 0; mt < 4; mt++)
#pragma unroll
        for (int nt = 0; nt < 8; nt++)
#pragma unroll
            for (int j = 0; j < 4; j++) acc[mt][nt][j] = 0.f;

    const int a_row = lane & 15, a_ch = lane >> 4;
    const int b_nin = (lane & 7) + ((lane >= 16) ? 8 : 0);
    const int b_ch  = (lane >> 3) & 1;

#define LOADC(cc, st) do { \
    const int _kc = (cc); \
    __half* _sa = gsm + (st) * STAGE; \
    const __half* _ah = Ahb + (size_t)_kc * BKC; \
    const __half* _al = Alb + (size_t)_kc * BKC; \
    const __half* _wf = Wfb + (size_t)_kc * BKC; \
    _Pragma("unroll") \
    for (int _i = 0; _i < 8; _i++) { \
        int _idx = tid + _i * 256; int _r = _idx >> 3, _s = _idx & 7; \
        cp_async16(smem_to_u32(&_sa[_r * LDSB + _s * 8]), _ah + (size_t)_r * EDIM + _s * 8); \
        cp_async16(smem_to_u32(&_sa[A2OFF + _r * LDSB + _s * 8]), _al + (size_t)_r * EDIM + _s * 8); \
    } \
    _Pragma("unroll") \
    for (int _i = 0; _i < 4; _i++) { \
        int _idx = tid + _i * 256; int _r = _idx >> 3, _s = _idx & 7; \
        cp_async16(smem_to_u32(&_sa[WFOFF + _r * LDSB + _s * 8]), _wf + (size_t)_r * EDIM + _s * 8); \
    } \
} while (0)

    const int NCH = EDIM / BKC;          // 16
    LOADC(0, 0); CP_COMMIT();

    for (int c = 0; c < NCH; c++) {
        CP_WAIT0();
        __syncthreads();
        if (c + 1 < NCH) { LOADC(c + 1, (c + 1) & 1); CP_COMMIT(); }

        const __half* st = gsm + (c & 1) * STAGE;
#pragma unroll
        for (int ks = 0; ks < 4; ks++) {
            const int k0 = ks * 16;
            uint32_t wf2[8][2];
#pragma unroll
            for (int p = 0; p < 4; p++) {
                uint32_t base = (wn + p * 16 + b_nin) * LDSB + k0 + b_ch * 8;
                uint32_t r0, r1, r2, r3;
                ldsm4(r0, r1, r2, r3, smem_to_u32(&st[WFOFF + base]));
                wf2[2*p][0] = r0; wf2[2*p][1] = r1; wf2[2*p+1][0] = r2; wf2[2*p+1][1] = r3;
            }
#pragma unroll
            for (int mt = 0; mt < 4; mt++) {
                uint32_t ahf[4], alf[4];
                uint32_t base = (wm + mt * 16 + a_row) * LDSB + k0 + a_ch * 8;
                ldsm4(ahf[0], ahf[1], ahf[2], ahf[3], smem_to_u32(&st[base]));
                ldsm4(alf[0], alf[1], alf[2], alf[3], smem_to_u32(&st[A2OFF + base]));
#pragma unroll
                for (int nt = 0; nt < 8; nt++)
                    mma16816h(acc[mt][nt], ahf[0], ahf[1], ahf[2], ahf[3],
                              wf2[nt][0], wf2[nt][1]);
#pragma unroll
                for (int nt = 0; nt < 8; nt++)
                    mma16816h(acc[mt][nt], alf[0], alf[1], alf[2], alf[3],
                              wf2[nt][0], wf2[nt][1]);
            }
        }
    }
#undef LOADC

    if (fp16out) {
        __half* O = (z == 0) ? O0 : (z == 1) ? O1 : O2;
#pragma unroll
        for (int nt = 0; nt < 8; nt++) {
            const int col = bn + wn + nt * 8 + (lane & 3) * 2;
            const float c0 = bias[col], c1 = bias[col + 1];
#pragma unroll
            for (int mt = 0; mt < 4; mt++) {
                const int r0 = bm + wm + mt * 16 + (lane >> 2);
#pragma unroll
                for (int rr = 0; rr < 2; rr++) {
                    float vx = (acc[mt][nt][2*rr+0] + c0) * scale;
                    float vy = (acc[mt][nt][2*rr+1] + c1) * scale;
                    size_t off = (size_t)(r0 + rr*8) * EDIM + col;
                    *(uint32_t*)(O + off) = packh2(vx, vy);
                }
            }
        }
    } else {
#pragma unroll
        for (int nt = 0; nt < 8; nt++) {
            const int col = bn + wn + nt * 8 + (lane & 3) * 2;
            const float c0 = bias[col], c1 = bias[col + 1];
#pragma unroll
            for (int mt = 0; mt < 4; mt++) {
                const int r0 = bm + wm + mt * 16 + (lane >> 2);
                *(float2*)&Cf[(size_t)r0 * EDIM + col] =
                    make_float2((acc[mt][nt][0] + c0) * scale, (acc[mt][nt][1] + c1) * scale);
                *(float2*)&Cf[(size_t)(r0 + 8) * EDIM + col] =
                    make_float2((acc[mt][nt][2] + c0) * scale, (acc[mt][nt][3] + c1) * scale);
            }
        }
    }
}

// ---------------- sliding-window flash attention, fp16 (S 1-pass, PV 2-pass) ----
#define ALDA 72
#define ATT_SMEM ((64 + 2*2*64) * ALDA * 2)   // Q + 2 bufs x (K,V) = 46,080 B

__global__ __launch_bounds__(128, 2)
void swattn_tc(const __half* __restrict__ Qf, const __half* __restrict__ Kf,
               const __half* __restrict__ Vf,
               __half* __restrict__ Oh, __half* __restrict__ Ol)
{
    extern __shared__ __align__(16) __half sb[];
    __half* Qs = sb;
    __half* KV = Qs + 64 * ALDA;              // [buf][2][64*ALDA]

    const int tid = threadIdx.x, wid = tid >> 5, lane = tid & 31;
    const int qt = blockIdx.x, h = blockIdx.y, b = blockIdx.z;
    const int q0 = qt * 64;
    const size_t base = (size_t)b * SEQ * EDIM + (size_t)h * HD;
    const int kb0 = (qt > 4) ? qt - 4 : 0;
    const int NB  = qt - kb0 + 1;

    // Q load: 64 rows x 8 segs = 512 units / 128 threads
#pragma unroll
    for (int i = 0; i < 4; i++) {
        int idx = tid + i * 128;
        int r = idx >> 3, s = idx & 7;
        cp_async16(smem_to_u32(Qs + r * ALDA + s * 8),
                   Qf + base + (size_t)(q0 + r) * EDIM + s * 8);
    }
    CP_COMMIT();

#define ALOAD_KV(kb, buf) do { \
    const __half* _srcs[2] = {Kf, Vf}; \
    __half* _d = KV + (buf) * 2 * 64 * ALDA; \
    _Pragma("unroll") \
    for (int _i = 0; _i < 8; _i++) { \
        int _idx = tid + _i * 128; \
        int _t = _idx >> 9, _r = (_idx >> 3) & 63, _s = _idx & 7; \
        cp_async16(smem_to_u32(_d + _t * 64 * ALDA + _r * ALDA + _s * 8), \
                   _srcs[_t] + base + (size_t)((kb) * 64 + _r) * EDIM + _s * 8); \
    } \
} while (0)

    ALOAD_KV(kb0, 0); CP_COMMIT();
    if (NB >= 2) { ALOAD_KV(kb0 + 1, 1); CP_COMMIT(); }

    const int b_nin = (lane & 7) + ((lane >= 16) ? 8 : 0);
    const int b_ch  = (lane >> 3) & 1;

    uint32_t qf[4][4];
    float o[8][4];
#pragma unroll
    for (int nt = 0; nt < 8; nt++)
#pragma unroll
        for (int j = 0; j < 4; j++) o[nt][j] = 0.f;
    float m0 = -1e30f, m1 = -1e30f, l0 = 0.f, l1 = 0.f;
    const int i0 = q0 + wid * 16 + (lane >> 2);

    for (int j = 0; j < NB; j++) {
        if (j + 1 < NB) CP_WAIT1(); else CP_WAIT0();
        __syncthreads();
        if (j == 0) {
#pragma unroll
            for (int kt = 0; kt < 4; kt++) {
                uint32_t a = smem_to_u32(&Qs[(wid*16 + (lane & 15)) * ALDA + kt*16 + (lane >> 4)*8]);
                ldsm4(qf[kt][0], qf[kt][1], qf[kt][2], qf[kt][3], a);
            }
        }
        const int kb = kb0 + j;
        const __half* khs = KV + (j & 1) * 2 * 64 * ALDA;
        const __half* vhs = khs + 64 * ALDA;

        // ---- S = Q K^T, single pass ----
        float s[8][4];
#pragma unroll
        for (int nt = 0; nt < 8; nt++)
#pragma unroll
            for (int c = 0; c < 4; c++) s[nt][c] = 0.f;

#pragma unroll
        for (int kt = 0; kt < 4; kt++) {
            uint32_t bk[8][2];
#pragma unroll
            for (int p = 0; p < 4; p++) {
                uint32_t r0, r1, r2, r3;
                uint32_t addr = smem_to_u32(&khs[(p*16 + b_nin) * ALDA + kt*16 + b_ch*8]);
                ldsm4(r0, r1, r2, r3, addr);
                bk[2*p][0] = r0; bk[2*p][1] = r1; bk[2*p+1][0] = r2; bk[2*p+1][1] = r3;
            }
#pragma unroll
            for (int nt = 0; nt < 8; nt++)
                mma16816h(s[nt], qf[kt][0], qf[kt][1], qf[kt][2], qf[kt][3],
                          bk[nt][0], bk[nt][1]);
        }

        // ---- mask + online softmax ----
        float mxA = -1e30f, mxB = -1e30f;
#pragma unroll
        for (int nt = 0; nt < 8; nt++) {
            int jb = kb * 64 + nt * 8 + (lane & 3) * 2;
            int d0 = i0 - jb;
            if ((unsigned)d0       > 256u) s[nt][0] = -1e30f;
            if ((unsigned)(d0 - 1) > 256u) s[nt][1] = -1e30f;
            if ((unsigned)(d0 + 8) > 256u) s[nt][2] = -1e30f;
            if ((unsigned)(d0 + 7) > 256u) s[nt][3] = -1e30f;
            mxA = fmaxf(mxA, fmaxf(s[nt][0], s[nt][1]));
            mxB = fmaxf(mxB, fmaxf(s[nt][2], s[nt][3]));
        }
        mxA = fmaxf(mxA, __shfl_xor_sync(0xffffffffu, mxA, 1));
        mxA = fmaxf(mxA, __shfl_xor_sync(0xffffffffu, mxA, 2));
        mxB = fmaxf(mxB, __shfl_xor_sync(0xffffffffu, mxB, 1));
        mxB = fmaxf(mxB, __shfl_xor_sync(0xffffffffu, mxB, 2));
        float nm0 = fmaxf(m0, mxA), nm1 = fmaxf(m1, mxB);
        float al0 = __expf(m0 - nm0), al1 = __expf(m1 - nm1);
        m0 = nm0; m1 = nm1;
        float rs0 = 0.f, rs1 = 0.f;
#pragma unroll
        for (int nt = 0; nt < 8; nt++) {
            s[nt][0] = __expf(s[nt][0] - m0);
            s[nt][1] = __expf(s[nt][1] - m0);
            s[nt][2] = __expf(s[nt][2] - m1);
            s[nt][3] = __expf(s[nt][3] - m1);
            rs0 += s[nt][0] + s[nt][1];
            rs1 += s[nt][2] + s[nt][3];
            o[nt][0] *= al0; o[nt][1] *= al0; o[nt][2] *= al1; o[nt][3] *= al1;
        }
        rs0 += __shfl_xor_sync(0xffffffffu, rs0, 1);
        rs0 += __shfl_xor_sync(0xffffffffu, rs0, 2);
        rs1 += __shfl_xor_sync(0xffffffffu, rs1, 1);
        rs1 += __shfl_xor_sync(0xffffffffu, rs1, 2);
        l0 = l0 * al0 + rs0;
        l1 = l1 * al1 + rs1;

        // ---- O += (Ph + Pl) @ V, 2 passes ----
#pragma unroll
        for (int kt = 0; kt < 4; kt++) {
            uint32_t pha[4], pla[4];
            {
                const int t0 = 2 * kt, t1 = 2 * kt + 1;
                __half h00 = __float2half_rn(s[t0][0]);
                __half h01 = __float2half_rn(s[t0][1]);
                __half h02 = __float2half_rn(s[t0][2]);
                __half h03 = __float2half_rn(s[t0][3]);
                __half h10 = __float2half_rn(s[t1][0]);
                __half h11 = __float2half_rn(s[t1][1]);
                __half h12 = __float2half_rn(s[t1][2]);
                __half h13 = __float2half_rn(s[t1][3]);
                pha[0] = ((uint32_t)*(uint16_t*)&h01 << 16) | *(uint16_t*)&h00;
                pha[1] = ((uint32_t)*(uint16_t*)&h03 << 16) | *(uint16_t*)&h02;
                pha[2] = ((uint32_t)*(uint16_t*)&h11 << 16) | *(uint16_t*)&h10;
                pha[3] = ((uint32_t)*(uint16_t*)&h13 << 16) | *(uint16_t*)&h12;
                pla[0] = packh2(s[t0][0] - __half2float(h00), s[t0][1] - __half2float(h01));
                pla[1] = packh2(s[t0][2] - __half2float(h02), s[t0][3] - __half2float(h03));
                pla[2] = packh2(s[t1][0] - __half2float(h10), s[t1][1] - __half2float(h11));
                pla[3] = packh2(s[t1][2] - __half2float(h12), s[t1][3] - __half2float(h13));
            }
#pragma unroll
            for (int p = 0; p < 4; p++) {
                uint32_t vrow = (kt*16 + ((lane >> 3) & 1)*8 + (lane & 7)) * ALDA + (p*2 + (lane >> 4))*8;
                uint32_t r0, r1, r2, r3;
                ldsm4t(r0, r1, r2, r3, smem_to_u32(&vhs[vrow]));
                mma16816h(o[2*p],   pha[0], pha[1], pha[2], pha[3], r0, r1);
                mma16816h(o[2*p],   pla[0], pla[1], pla[2], pla[3], r0, r1);
                mma16816h(o[2*p+1], pha[0], pha[1], pha[2], pha[3], r2, r3);
                mma16816h(o[2*p+1], pla[0], pla[1], pla[2], pla[3], r2, r3);
            }
        }

        __syncthreads();
        if (j + 2 < NB) { ALOAD_KV(kb0 + j + 2, j & 1); CP_COMMIT(); }
    }
#undef ALOAD_KV

    // epilogue: write fp16 hi/lo y for the Wo GEMM
    const float inv0 = 1.0f / l0, inv1 = 1.0f / l1;
#pragma unroll
    for (int nt = 0; nt < 8; nt++) {
        const int col = nt * 8 + (lane & 3) * 2;
        float v0 = o[nt][0] * inv0, v1 = o[nt][1] * inv0;
        float v2 = o[nt][2] * inv1, v3 = o[nt][3] * inv1;
        __half h0 = __float2half_rn(v0), h1 = __float2half_rn(v1);
        __half h2 = __float2half_rn(v2), h3 = __float2half_rn(v3);
        size_t off0 = base + (size_t)i0 * EDIM + col;
        size_t off1 = base + (size_t)(i0 + 8) * EDIM + col;
        *(uint32_t*)(Oh + off0) = ((uint32_t)*(uint16_t*)&h1 << 16) | *(uint16_t*)&h0;
        *(uint32_t*)(Oh + off1) = ((uint32_t)*(uint16_t*)&h3 << 16) | *(uint16_t*)&h2;
        *(uint32_t*)(Ol + off0) = packh2(v0 - __half2float(h0), v1 - __half2float(h1));
        *(uint32_t*)(Ol + off1) = packh2(v2 - __half2float(h2), v3 - __half2float(h3));
    }
}

// ---------------- launch ----------------
extern "C" void kernel_launch(void* const* d_in, const int* in_sizes, int n_in,
                              void* d_out, int out_size)
{
    const float* x  = (const float*)d_in[0];
    const float* Wq = (const float*)d_in[1];
    const float* Wk = (const float*)d_in[2];
    const float* Wv = (const float*)d_in[3];
    const float* Wo = (const float*)d_in[4];
    const float* bq = (const float*)d_in[5];
    const float* bk = (const float*)d_in[6];
    const float* bv = (const float*)d_in[7];
    const float* bo = (const float*)d_in[8];

    __half *xh, *xl, *qf, *kf, *vf, *yh, *yl, *wf;
    cudaGetSymbolAddress((void**)&xh, g_xh);
    cudaGetSymbolAddress((void**)&xl, g_xl);
    cudaGetSymbolAddress((void**)&qf, g_qf);
    cudaGetSymbolAddress((void**)&kf, g_kf);
    cudaGetSymbolAddress((void**)&vf, g_vf);
    cudaGetSymbolAddress((void**)&yh, g_yh);
    cudaGetSymbolAddress((void**)&yl, g_yl);
    cudaGetSymbolAddress((void**)&wf, g_wf);

    static bool attr_done = false;
    if (!attr_done) {
        cudaFuncSetAttribute(gemm_tc2,  cudaFuncAttributeMaxDynamicSharedMemorySize, GEMM_SMEM);
        cudaFuncSetAttribute(swattn_tc, cudaFuncAttributeMaxDynamicSharedMemorySize, ATT_SMEM);
        attr_done = true;
    }

    const int NX4 = MROWS * EDIM / 4;   // 1,048,576
    const int NW4 = EDIM * EDIM / 4;    //   262,144
    const size_t WSZ = (size_t)EDIM * EDIM;

    split5<<<dim3((NX4 + 255) / 256, 5), 256>>>(
        x, Wq, Wk, Wv, Wo, xh, xl, wf, NX4, NW4);

    // fused QKV projection -> single fp16 q,k,v (q pre-scaled by 1/8)
    gemm_tc2<<<dim3(EDIM/BN, MROWS/BM, 3), 256, GEMM_SMEM>>>(
        xh, xl, wf, bq, bk, bv, nullptr,
        qf, kf, vf, 0.125f, 1);

    swattn_tc<<<dim3(SEQ/64, HEADS, BATCH), 128, ATT_SMEM>>>(
        qf, kf, vf, yh, yl);

    // output projection -> fp32 d_out
    gemm_tc2<<<dim3(EDIM/BN, MROWS/BM, 1), 256, GEMM_SMEM>>>(
        yh, yl, wf + 3*WSZ, bo, nullptr, nullptr,
        (float*)d_out, nullptr, nullptr, nullptr, 1.0f, 0);
}

// round 14
// speedup vs baseline: 2.1060x; 1.3344x over previous
#include <cuda_runtime.h>
#include <cuda_bf16.h>
#include <cuda_fp16.h>
#include <cstdint>

#define EDIM  1024
#define HEADS 16
#define HD    64
#define WIN   256
#define BATCH 2
#define SEQ   2048
#define MROWS (BATCH*SEQ)   // 4096

// ---------------- scratch (allocation-free rule: device globals) ----------------
static __device__ __half g_xf[MROWS*EDIM];
static __device__ __half g_qf[MROWS*EDIM];
static __device__ __half g_kf[MROWS*EDIM];
static __device__ __half g_vf[MROWS*EDIM];
static __device__ __half g_yh[MROWS*EDIM];
static __device__ __half g_yl[MROWS*EDIM];
static __device__ __half g_wf[4][EDIM*EDIM];

// ---------------- family-common PTX helpers ----------------
__device__ __forceinline__ uint32_t smem_to_u32(const void* p) {
    uint32_t a;
    asm("{ .reg .u64 t; cvta.to.shared.u64 t, %1; cvt.u32.u64 %0, t; }"
        : "=r"(a) : "l"(p));
    return a;
}
__device__ __forceinline__ void cp_async16(uint32_t dst, const void* src) {
    asm volatile("cp.async.cg.shared.global [%0], [%1], 16;" :: "r"(dst), "l"(src));
}
#define CP_COMMIT() asm volatile("cp.async.commit_group;" ::: "memory")
#define CP_WAIT1()  asm volatile("cp.async.wait_group 1;" ::: "memory")
#define CP_WAIT0()  asm volatile("cp.async.wait_group 0;" ::: "memory")

__device__ __forceinline__ void ldsm4(uint32_t& r0, uint32_t& r1, uint32_t& r2,
                                      uint32_t& r3, uint32_t addr) {
    asm volatile("ldmatrix.sync.aligned.m8n8.x4.shared.b16 {%0,%1,%2,%3}, [%4];"
                 : "=r"(r0), "=r"(r1), "=r"(r2), "=r"(r3) : "r"(addr));
}
__device__ __forceinline__ void ldsm4t(uint32_t& r0, uint32_t& r1, uint32_t& r2,
                                       uint32_t& r3, uint32_t addr) {
    asm volatile("ldmatrix.sync.aligned.m8n8.x4.trans.shared.b16 {%0,%1,%2,%3}, [%4];"
                 : "=r"(r0), "=r"(r1), "=r"(r2), "=r"(r3) : "r"(addr));
}
__device__ __forceinline__ void mma16816h(float* c, uint32_t a0, uint32_t a1,
                                          uint32_t a2, uint32_t a3,
                                          uint32_t b0, uint32_t b1) {
    asm volatile(
        "mma.sync.aligned.m16n8k16.row.col.f32.f16.f16.f32 "
        "{%0,%1,%2,%3}, {%4,%5,%6,%7}, {%8,%9}, {%0,%1,%2,%3};"
        : "+f"(c[0]), "+f"(c[1]), "+f"(c[2]), "+f"(c[3])
        : "r"(a0), "r"(a1), "r"(a2), "r"(a3), "r"(b0), "r"(b1));
}
__device__ __forceinline__ uint32_t packh2(float a, float b) {
    __half2 t = __floats2half2_rn(a, b);
    return *(uint32_t*)&t;
}

// ---------------- fused fp32 -> fp16 convert (x and 4 W slabs, single fp16) ----
__global__ __launch_bounds__(256)
void split5(const float* __restrict__ s0, const float* __restrict__ s1,
            const float* __restrict__ s2, const float* __restrict__ s3,
            const float* __restrict__ s4,
            __half* __restrict__ xf, __half* __restrict__ wf, int n0, int nw)
{
    const int t = blockIdx.y;
    const int n4 = (t == 0) ? n0 : nw;
    int i = blockIdx.x * 256 + threadIdx.x;
    if (i >= n4) return;
    const float* in = (t == 0) ? s0 : (t == 1) ? s1 : (t == 2) ? s2 : (t == 3) ? s3 : s4;
    float4 v = ((const float4*)in)[i];
    float vv[4] = {v.x, v.y, v.z, v.w};
    __half h[4];
#pragma unroll
    for (int j = 0; j < 4; j++) h[j] = __float2half_rn(vv[j]);
    __half* dst = (t == 0) ? xf : (wf + (size_t)(t - 1) * EDIM * EDIM);
    ((uint2*)dst)[i] = *(uint2*)h;
}

// ---------------- fp16 warp-MMA GEMM, 1 or 2 pass (A possibly hi+lo) ----------
#define BM   256
#define BN   128
#define BKC  64
#define LDSB 72
#define A2OFF (256*LDSB)
#define WFOFF (512*LDSB)
#define STAGE (640*LDSB)
#define GEMM_SMEM (2*STAGE*2)            // 184,320 B -> 1 CTA/SM, 8 warps

__global__ __launch_bounds__(256, 1)
void gemm_tc2(const __half* __restrict__ Ah, const __half* __restrict__ Al,
              const __half* __restrict__ Wf,
              const float* __restrict__ b0v, const float* __restrict__ b1v,
              const float* __restrict__ b2v,
              float* __restrict__ Cf,
              __half* __restrict__ O0, __half* __restrict__ O1, __half* __restrict__ O2,
              float s0, int fp16out, int two_pass)
{
    extern __shared__ __align__(16) __half gsm[];

    const int tid  = threadIdx.x;
    const int wid  = tid >> 5;
    const int lane = tid & 31;
    const int bm   = blockIdx.y * BM;
    const int bn   = blockIdx.x * BN;
    const int z    = blockIdx.z;
    const int wm   = (wid & 3) * 64;
    const int wn   = (wid >> 2) * 64;

    const __half* Wfb = Wf + (size_t)z * EDIM * EDIM + (size_t)bn * EDIM;
    const __half* Ahb = Ah + (size_t)bm * EDIM;
    const __half* Alb = two_pass ? (Al + (size_t)bm * EDIM) : nullptr;
    const float* bias = (z == 0) ? b0v : (z == 1) ? b1v : b2v;
    const float scale = (z == 0) ? s0 : 1.0f;

    float acc[4][8][4];
#pragma unroll
    for (int mt = 0; mt < 4; mt++)
#pragma unroll
        for (int nt = 0; nt < 8; nt++)
#pragma unroll
            for (int j = 0; j < 4; j++) acc[mt][nt][j] = 0.f;

    const int a_row = lane & 15, a_ch = lane >> 4;
    const int b_nin = (lane & 7) + ((lane >= 16) ? 8 : 0);
    const int b_ch  = (lane >> 3) & 1;

#define LOADC(cc, st) do { \
    const int _kc = (cc); \
    __half* _sa = gsm + (st) * STAGE; \
    const __half* _ah = Ahb + (size_t)_kc * BKC; \
    const __half* _wf = Wfb + (size_t)_kc * BKC; \
    _Pragma("unroll") \
    for (int _i = 0; _i < 8; _i++) { \
        int _idx = tid + _i * 256; int _r = _idx >> 3, _s = _idx & 7; \
        cp_async16(smem_to_u32(&_sa[_r * LDSB + _s * 8]), _ah + (size_t)_r * EDIM + _s * 8); \
    } \
    if (two_pass) { \
        const __half* _al = Alb + (size_t)_kc * BKC; \
        _Pragma("unroll") \
        for (int _i = 0; _i < 8; _i++) { \
            int _idx = tid + _i * 256; int _r = _idx >> 3, _s = _idx & 7; \
            cp_async16(smem_to_u32(&_sa[A2OFF + _r * LDSB + _s * 8]), _al + (size_t)_r * EDIM + _s * 8); \
        } \
    } \
    _Pragma("unroll") \
    for (int _i = 0; _i < 4; _i++) { \
        int _idx = tid + _i * 256; int _r = _idx >> 3, _s = _idx & 7; \
        cp_async16(smem_to_u32(&_sa[WFOFF + _r * LDSB + _s * 8]), _wf + (size_t)_r * EDIM + _s * 8); \
    } \
} while (0)

    const int NCH = EDIM / BKC;          // 16
    LOADC(0, 0); CP_COMMIT();

    for (int c = 0; c < NCH; c++) {
        CP_WAIT0();
        __syncthreads();
        if (c + 1 < NCH) { LOADC(c + 1, (c + 1) & 1); CP_COMMIT(); }

        const __half* st = gsm + (c & 1) * STAGE;
#pragma unroll
        for (int ks = 0; ks < 4; ks++) {
            const int k0 = ks * 16;
            uint32_t wf2[8][2];
#pragma unroll
            for (int p = 0; p < 4; p++) {
                uint32_t base = (wn + p * 16 + b_nin) * LDSB + k0 + b_ch * 8;
                uint32_t r0, r1, r2, r3;
                ldsm4(r0, r1, r2, r3, smem_to_u32(&st[WFOFF + base]));
                wf2[2*p][0] = r0; wf2[2*p][1] = r1; wf2[2*p+1][0] = r2; wf2[2*p+1][1] = r3;
            }
#pragma unroll
            for (int mt = 0; mt < 4; mt++) {
                uint32_t ahf[4];
                uint32_t base = (wm + mt * 16 + a_row) * LDSB + k0 + a_ch * 8;
                ldsm4(ahf[0], ahf[1], ahf[2], ahf[3], smem_to_u32(&st[base]));
#pragma unroll
                for (int nt = 0; nt < 8; nt++)
                    mma16816h(acc[mt][nt], ahf[0], ahf[1], ahf[2], ahf[3],
                              wf2[nt][0], wf2[nt][1]);
                if (two_pass) {
                    uint32_t alf[4];
                    ldsm4(alf[0], alf[1], alf[2], alf[3], smem_to_u32(&st[A2OFF + base]));
#pragma unroll
                    for (int nt = 0; nt < 8; nt++)
                        mma16816h(acc[mt][nt], alf[0], alf[1], alf[2], alf[3],
                                  wf2[nt][0], wf2[nt][1]);
                }
            }
        }
    }
#undef LOADC

    if (fp16out) {
        __half* O = (z == 0) ? O0 : (z == 1) ? O1 : O2;
#pragma unroll
        for (int nt = 0; nt < 8; nt++) {
            const int col = bn + wn + nt * 8 + (lane & 3) * 2;
            const float c0 = bias[col], c1 = bias[col + 1];
#pragma unroll
            for (int mt = 0; mt < 4; mt++) {
                const int r0 = bm + wm + mt * 16 + (lane >> 2);
#pragma unroll
                for (int rr = 0; rr < 2; rr++) {
                    float vx = (acc[mt][nt][2*rr+0] + c0) * scale;
                    float vy = (acc[mt][nt][2*rr+1] + c1) * scale;
                    size_t off = (size_t)(r0 + rr*8) * EDIM + col;
                    *(uint32_t*)(O + off) = packh2(vx, vy);
                }
            }
        }
    } else {
#pragma unroll
        for (int nt = 0; nt < 8; nt++) {
            const int col = bn + wn + nt * 8 + (lane & 3) * 2;
            const float c0 = bias[col], c1 = bias[col + 1];
#pragma unroll
            for (int mt = 0; mt < 4; mt++) {
                const int r0 = bm + wm + mt * 16 + (lane >> 2);
                *(float2*)&Cf[(size_t)r0 * EDIM + col] =
                    make_float2((acc[mt][nt][0] + c0) * scale, (acc[mt][nt][1] + c1) * scale);
                *(float2*)&Cf[(size_t)(r0 + 8) * EDIM + col] =
                    make_float2((acc[mt][nt][2] + c0) * scale, (acc[mt][nt][3] + c1) * scale);
            }
        }
    }
}

// ---------------- sliding-window flash attention, fp16 (S 1-pass, PV 2-pass) ----
#define ALDA 72
#define ATT_SMEM ((64 + 2*2*64) * ALDA * 2)   // 46,080 B

__global__ __launch_bounds__(128, 2)
void swattn_tc(const __half* __restrict__ Qf, const __half* __restrict__ Kf,
               const __half* __restrict__ Vf,
               __half* __restrict__ Oh, __half* __restrict__ Ol)
{
    extern __shared__ __align__(16) __half sb[];
    __half* Qs = sb;
    __half* KV = Qs + 64 * ALDA;

    const int tid = threadIdx.x, wid = tid >> 5, lane = tid & 31;
    const int qt = blockIdx.x, h = blockIdx.y, b = blockIdx.z;
    const int q0 = qt * 64;
    const size_t base = (size_t)b * SEQ * EDIM + (size_t)h * HD;
    const int kb0 = (qt > 4) ? qt - 4 : 0;
    const int NB  = qt - kb0 + 1;

#pragma unroll
    for (int i = 0; i < 4; i++) {
        int idx = tid + i * 128;
        int r = idx >> 3, s = idx & 7;
        cp_async16(smem_to_u32(Qs + r * ALDA + s * 8),
                   Qf + base + (size_t)(q0 + r) * EDIM + s * 8);
    }
    CP_COMMIT();

#define ALOAD_KV(kb, buf) do { \
    const __half* _srcs[2] = {Kf, Vf}; \
    __half* _d = KV + (buf) * 2 * 64 * ALDA; \
    _Pragma("unroll") \
    for (int _i = 0; _i < 8; _i++) { \
        int _idx = tid + _i * 128; \
        int _t = _idx >> 9, _r = (_idx >> 3) & 63, _s = _idx & 7; \
        cp_async16(smem_to_u32(_d + _t * 64 * ALDA + _r * ALDA + _s * 8), \
                   _srcs[_t] + base + (size_t)((kb) * 64 + _r) * EDIM + _s * 8); \
    } \
} while (0)

    ALOAD_KV(kb0, 0); CP_COMMIT();
    if (NB >= 2) { ALOAD_KV(kb0 + 1, 1); CP_COMMIT(); }

    const int b_nin = (lane & 7) + ((lane >= 16) ? 8 : 0);
    const int b_ch  = (lane >> 3) & 1;

    uint32_t qf[4][4];
    float o[8][4];
#pragma unroll
    for (int nt = 0; nt < 8; nt++)
#pragma unroll
        for (int j = 0; j < 4; j++) o[nt][j] = 0.f;
    float m0 = -1e30f, m1 = -1e30f, l0 = 0.f, l1 = 0.f;
    const int i0 = q0 + wid * 16 + (lane >> 2);

    for (int j = 0; j < NB; j++) {
        if (j + 1 < NB) CP_WAIT1(); else CP_WAIT0();
        __syncthreads();
        if (j == 0) {
#pragma unroll
            for (int kt = 0; kt < 4; kt++) {
                uint32_t a = smem_to_u32(&Qs[(wid*16 + (lane & 15)) * ALDA + kt*16 + (lane >> 4)*8]);
                ldsm4(qf[kt][0], qf[kt][1], qf[kt][2], qf[kt][3], a);
            }
        }
        const int kb = kb0 + j;
        const __half* khs = KV + (j & 1) * 2 * 64 * ALDA;
        const __half* vhs = khs + 64 * ALDA;

        float s[8][4];
#pragma unroll
        for (int nt = 0; nt < 8; nt++)
#pragma unroll
            for (int c = 0; c < 4; c++) s[nt][c] = 0.f;

#pragma unroll
        for (int kt = 0; kt < 4; kt++) {
            uint32_t bk[8][2];
#pragma unroll
            for (int p = 0; p < 4; p++) {
                uint32_t r0, r1, r2, r3;
                uint32_t addr = smem_to_u32(&khs[(p*16 + b_nin) * ALDA + kt*16 + b_ch*8]);
                ldsm4(r0, r1, r2, r3, addr);
                bk[2*p][0] = r0; bk[2*p][1] = r1; bk[2*p+1][0] = r2; bk[2*p+1][1] = r3;
            }
#pragma unroll
            for (int nt = 0; nt < 8; nt++)
                mma16816h(s[nt], qf[kt][0], qf[kt][1], qf[kt][2], qf[kt][3],
                          bk[nt][0], bk[nt][1]);
        }

        float mxA = -1e30f, mxB = -1e30f;
#pragma unroll
        for (int nt = 0; nt < 8; nt++) {
            int jb = kb * 64 + nt * 8 + (lane & 3) * 2;
            int d0 = i0 - jb;
            if ((unsigned)d0       > 256u) s[nt][0] = -1e30f;
            if ((unsigned)(d0 - 1) > 256u) s[nt][1] = -1e30f;
            if ((unsigned)(d0 + 8) > 256u) s[nt][2] = -1e30f;
            if ((unsigned)(d0 + 7) > 256u) s[nt][3] = -1e30f;
            mxA = fmaxf(mxA, fmaxf(s[nt][0], s[nt][1]));
            mxB = fmaxf(mxB, fmaxf(s[nt][2], s[nt][3]));
        }
        mxA = fmaxf(mxA, __shfl_xor_sync(0xffffffffu, mxA, 1));
        mxA = fmaxf(mxA, __shfl_xor_sync(0xffffffffu, mxA, 2));
        mxB = fmaxf(mxB, __shfl_xor_sync(0xffffffffu, mxB, 1));
        mxB = fmaxf(mxB, __shfl_xor_sync(0xffffffffu, mxB, 2));
        float nm0 = fmaxf(m0, mxA), nm1 = fmaxf(m1, mxB);
        float al0 = __expf(m0 - nm0), al1 = __expf(m1 - nm1);
        m0 = nm0; m1 = nm1;
        float rs0 = 0.f, rs1 = 0.f;
#pragma unroll
        for (int nt = 0; nt < 8; nt++) {
            s[nt][0] = __expf(s[nt][0] - m0);
            s[nt][1] = __expf(s[nt][1] - m0);
            s[nt][2] = __expf(s[nt][2] - m1);
            s[nt][3] = __expf(s[nt][3] - m1);
            rs0 += s[nt][0] + s[nt][1];
            rs1 += s[nt][2] + s[nt][3];
            o[nt][0] *= al0; o[nt][1] *= al0; o[nt][2] *= al1; o[nt][3] *= al1;
        }
        rs0 += __shfl_xor_sync(0xffffffffu, rs0, 1);
        rs0 += __shfl_xor_sync(0xffffffffu, rs0, 2);
        rs1 += __shfl_xor_sync(0xffffffffu, rs1, 1);
        rs1 += __shfl_xor_sync(0xffffffffu, rs1, 2);
        l0 = l0 * al0 + rs0;
        l1 = l1 * al1 + rs1;

#pragma unroll
        for (int kt = 0; kt < 4; kt++) {
            uint32_t pha[4], pla[4];
            {
                const int t0 = 2 * kt, t1 = 2 * kt + 1;
                __half h00 = __float2half_rn(s[t0][0]);
                __half h01 = __float2half_rn(s[t0][1]);
                __half h02 = __float2half_rn(s[t0][2]);
                __half h03 = __float2half_rn(s[t0][3]);
                __half h10 = __float2half_rn(s[t1][0]);
                __half h11 = __float2half_rn(s[t1][1]);
                __half h12 = __float2half_rn(s[t1][2]);
                __half h13 = __float2half_rn(s[t1][3]);
                pha[0] = ((uint32_t)*(uint16_t*)&h01 << 16) | *(uint16_t*)&h00;
                pha[1] = ((uint32_t)*(uint16_t*)&h03 << 16) | *(uint16_t*)&h02;
                pha[2] = ((uint32_t)*(uint16_t*)&h11 << 16) | *(uint16_t*)&h10;
                pha[3] = ((uint32_t)*(uint16_t*)&h13 << 16) | *(uint16_t*)&h12;
                pla[0] = packh2(s[t0][0] - __half2float(h00), s[t0][1] - __half2float(h01));
                pla[1] = packh2(s[t0][2] - __half2float(h02), s[t0][3] - __half2float(h03));
                pla[2] = packh2(s[t1][0] - __half2float(h10), s[t1][1] - __half2float(h11));
                pla[3] = packh2(s[t1][2] - __half2float(h12), s[t1][3] - __half2float(h13));
            }
#pragma unroll
            for (int p = 0; p < 4; p++) {
                uint32_t vrow = (kt*16 + ((lane >> 3) & 1)*8 + (lane & 7)) * ALDA + (p*2 + (lane >> 4))*8;
                uint32_t r0, r1, r2, r3;
                ldsm4t(r0, r1, r2, r3, smem_to_u32(&vhs[vrow]));
                mma16816h(o[2*p],   pha[0], pha[1], pha[2], pha[3], r0, r1);
                mma16816h(o[2*p],   pla[0], pla[1], pla[2], pla[3], r0, r1);
                mma16816h(o[2*p+1], pha[0], pha[1], pha[2], pha[3], r2, r3);
                mma16816h(o[2*p+1], pla[0], pla[1], pla[2], pla[3], r2, r3);
            }
        }

        __syncthreads();
        if (j + 2 < NB) { ALOAD_KV(kb0 + j + 2, j & 1); CP_COMMIT(); }
    }
#undef ALOAD_KV

    const float inv0 = 1.0f / l0, inv1 = 1.0f / l1;
#pragma unroll
    for (int nt = 0; nt < 8; nt++) {
        const int col = nt * 8 + (lane & 3) * 2;
        float v0 = o[nt][0] * inv0, v1 = o[nt][1] * inv0;
        float v2 = o[nt][2] * inv1, v3 = o[nt][3] * inv1;
        __half h0 = __float2half_rn(v0), h1 = __float2half_rn(v1);
        __half h2 = __float2half_rn(v2), h3 = __float2half_rn(v3);
        size_t off0 = base + (size_t)i0 * EDIM + col;
        size_t off1 = base + (size_t)(i0 + 8) * EDIM + col;
        *(uint32_t*)(Oh + off0) = ((uint32_t)*(uint16_t*)&h1 << 16) | *(uint16_t*)&h0;
        *(uint32_t*)(Oh + off1) = ((uint32_t)*(uint16_t*)&h3 << 16) | *(uint16_t*)&h2;
        *(uint32_t*)(Ol + off0) = packh2(v0 - __half2float(h0), v1 - __half2float(h1));
        *(uint32_t*)(Ol + off1) = packh2(v2 - __half2float(h2), v3 - __half2float(h3));
    }
}

// ---------------- launch ----------------
extern "C" void kernel_launch(void* const* d_in, const int* in_sizes, int n_in,
                              void* d_out, int out_size)
{
    const float* x  = (const float*)d_in[0];
    const float* Wq = (const float*)d_in[1];
    const float* Wk = (const float*)d_in[2];
    const float* Wv = (const float*)d_in[3];
    const float* Wo = (const float*)d_in[4];
    const float* bq = (const float*)d_in[5];
    const float* bk = (const float*)d_in[6];
    const float* bv = (const float*)d_in[7];
    const float* bo = (const float*)d_in[8];

    __half *xf, *qf, *kf, *vf, *yh, *yl, *wf;
    cudaGetSymbolAddress((void**)&xf, g_xf);
    cudaGetSymbolAddress((void**)&qf, g_qf);
    cudaGetSymbolAddress((void**)&kf, g_kf);
    cudaGetSymbolAddress((void**)&vf, g_vf);
    cudaGetSymbolAddress((void**)&yh, g_yh);
    cudaGetSymbolAddress((void**)&yl, g_yl);
    cudaGetSymbolAddress((void**)&wf, g_wf);

    static bool attr_done = false;
    if (!attr_done) {
        cudaFuncSetAttribute(gemm_tc2,  cudaFuncAttributeMaxDynamicSharedMemorySize, GEMM_SMEM);
        cudaFuncSetAttribute(swattn_tc, cudaFuncAttributeMaxDynamicSharedMemorySize, ATT_SMEM);
        attr_done = true;
    }

    const int NX4 = MROWS * EDIM / 4;   // 1,048,576
    const int NW4 = EDIM * EDIM / 4;    //   262,144
    const size_t WSZ = (size_t)EDIM * EDIM;

    split5<<<dim3((NX4 + 255) / 256, 5), 256>>>(
        x, Wq, Wk, Wv, Wo, xf, wf, NX4, NW4);

    // fused QKV projection: 1-pass fp16 (q pre-scaled by 1/8)
    gemm_tc2<<<dim3(EDIM/BN, MROWS/BM, 3), 256, GEMM_SMEM>>>(
        xf, nullptr, wf, bq, bk, bv, nullptr,
        qf, kf, vf, 0.125f, 1, 0);

    swattn_tc<<<dim3(SEQ/64, HEADS, BATCH), 128, ATT_SMEM>>>(
        qf, kf, vf, yh, yl);

    // output projection: 2-pass (y = yh + yl) -> fp32 d_out
    gemm_tc2<<<dim3(EDIM/BN, MROWS/BM, 1), 256, GEMM_SMEM>>>(
        yh, yl, wf + 3*WSZ, bo, nullptr, nullptr,
        (float*)d_out, nullptr, nullptr, nullptr, 1.0f, 0, 1);
}

// round 15
// speedup vs baseline: 2.4278x; 1.1528x over previous
#include <cuda_runtime.h>
#include <cuda_bf16.h>
#include <cuda_fp16.h>
#include <cstdint>

#define EDIM  1024
#define HEADS 16
#define HD    64
#define WIN   256
#define BATCH 2
#define SEQ   2048
#define MROWS (BATCH*SEQ)   // 4096

// ---------------- scratch (allocation-free rule: device globals) ----------------
static __device__ __half g_xf[MROWS*EDIM];
static __device__ __half g_qf[MROWS*EDIM];
static __device__ __half g_kf[MROWS*EDIM];
static __device__ __half g_vf[MROWS*EDIM];
static __device__ __half g_yf[MROWS*EDIM];
static __device__ __half g_wf[4][EDIM*EDIM];

// ---------------- family-common PTX helpers ----------------
__device__ __forceinline__ uint32_t smem_to_u32(const void* p) {
    uint32_t a;
    asm("{ .reg .u64 t; cvta.to.shared.u64 t, %1; cvt.u32.u64 %0, t; }"
        : "=r"(a) : "l"(p));
    return a;
}
__device__ __forceinline__ void cp_async16(uint32_t dst, const void* src) {
    asm volatile("cp.async.cg.shared.global [%0], [%1], 16;" :: "r"(dst), "l"(src));
}
#define CP_COMMIT() asm volatile("cp.async.commit_group;" ::: "memory")
#define CP_WAIT1()  asm volatile("cp.async.wait_group 1;" ::: "memory")
#define CP_WAIT0()  asm volatile("cp.async.wait_group 0;" ::: "memory")

__device__ __forceinline__ void ldsm4(uint32_t& r0, uint32_t& r1, uint32_t& r2,
                                      uint32_t& r3, uint32_t addr) {
    asm volatile("ldmatrix.sync.aligned.m8n8.x4.shared.b16 {%0,%1,%2,%3}, [%4];"
                 : "=r"(r0), "=r"(r1), "=r"(r2), "=r"(r3) : "r"(addr));
}
__device__ __forceinline__ void ldsm4t(uint32_t& r0, uint32_t& r1, uint32_t& r2,
                                       uint32_t& r3, uint32_t addr) {
    asm volatile("ldmatrix.sync.aligned.m8n8.x4.trans.shared.b16 {%0,%1,%2,%3}, [%4];"
                 : "=r"(r0), "=r"(r1), "=r"(r2), "=r"(r3) : "r"(addr));
}
__device__ __forceinline__ void mma16816h(float* c, uint32_t a0, uint32_t a1,
                                          uint32_t a2, uint32_t a3,
                                          uint32_t b0, uint32_t b1) {
    asm volatile(
        "mma.sync.aligned.m16n8k16.row.col.f32.f16.f16.f32 "
        "{%0,%1,%2,%3}, {%4,%5,%6,%7}, {%8,%9}, {%0,%1,%2,%3};"
        : "+f"(c[0]), "+f"(c[1]), "+f"(c[2]), "+f"(c[3])
        : "r"(a0), "r"(a1), "r"(a2), "r"(a3), "r"(b0), "r"(b1));
}
__device__ __forceinline__ uint32_t packh2(float a, float b) {
    __half2 t = __floats2half2_rn(a, b);
    return *(uint32_t*)&t;
}

// ---------------- fused fp32 -> fp16 convert (x and 4 W slabs) ----
__global__ __launch_bounds__(256)
void split5(const float* __restrict__ s0, const float* __restrict__ s1,
            const float* __restrict__ s2, const float* __restrict__ s3,
            const float* __restrict__ s4,
            __half* __restrict__ xf, __half* __restrict__ wf, int n0, int nw)
{
    const int t = blockIdx.y;
    const int n4 = (t == 0) ? n0 : nw;
    int i = blockIdx.x * 256 + threadIdx.x;
    if (i >= n4) return;
    const float* in = (t == 0) ? s0 : (t == 1) ? s1 : (t == 2) ? s2 : (t == 3) ? s3 : s4;
    float4 v = ((const float4*)in)[i];
    float vv[4] = {v.x, v.y, v.z, v.w};
    __half h[4];
#pragma unroll
    for (int j = 0; j < 4; j++) h[j] = __float2half_rn(vv[j]);
    __half* dst = (t == 0) ? xf : (wf + (size_t)(t - 1) * EDIM * EDIM);
    ((uint2*)dst)[i] = *(uint2*)h;
}

// ---------------- fp16 warp-MMA GEMM, 1 or 2 pass (A possibly hi+lo) ----------
#define BM   256
#define BN   128
#define BKC  64
#define LDSB 72
#define A2OFF (256*LDSB)
#define WFOFF (512*LDSB)
#define STAGE (640*LDSB)
#define GEMM_SMEM (2*STAGE*2)            // 184,320 B -> 1 CTA/SM, 8 warps

__global__ __launch_bounds__(256, 1)
void gemm_tc2(const __half* __restrict__ Ah, const __half* __restrict__ Al,
              const __half* __restrict__ Wf,
              const float* __restrict__ b0v, const float* __restrict__ b1v,
              const float* __restrict__ b2v,
              float* __restrict__ Cf,
              __half* __restrict__ O0, __half* __restrict__ O1, __half* __restrict__ O2,
              float s0, int fp16out, int two_pass)
{
    extern __shared__ __align__(16) __half gsm[];

    const int tid  = threadIdx.x;
    const int wid  = tid >> 5;
    const int lane = tid & 31;
    const int bm   = blockIdx.y * BM;
    const int bn   = blockIdx.x * BN;
    const int z    = blockIdx.z;
    const int wm   = (wid & 3) * 64;
    const int wn   = (wid >> 2) * 64;

    const __half* Wfb = Wf + (size_t)z * EDIM * EDIM + (size_t)bn * EDIM;
    const __half* Ahb = Ah + (size_t)bm * EDIM;
    const __half* Alb = two_pass ? (Al + (size_t)bm * EDIM) : nullptr;
    const float* bias = (z == 0) ? b0v : (z == 1) ? b1v : b2v;
    const float scale = (z == 0) ? s0 : 1.0f;

    float acc[4][8][4];
#pragma unroll
    for (int mt = 0; mt < 4; mt++)
#pragma unroll
        for (int nt = 0; nt < 8; nt++)
#pragma unroll
            for (int j = 0; j < 4; j++) acc[mt][nt][j] = 0.f;

    const int a_row = lane & 15, a_ch = lane >> 4;
    const int b_nin = (lane & 7) + ((lane >= 16) ? 8 : 0);
    const int b_ch  = (lane >> 3) & 1;

#define LOADC(cc, st) do { \
    const int _kc = (cc); \
    __half* _sa = gsm + (st) * STAGE; \
    const __half* _ah = Ahb + (size_t)_kc * BKC; \
    const __half* _wf = Wfb + (size_t)_kc * BKC; \
    _Pragma("unroll") \
    for (int _i = 0; _i < 8; _i++) { \
        int _idx = tid + _i * 256; int _r = _idx >> 3, _s = _idx & 7; \
        cp_async16(smem_to_u32(&_sa[_r * LDSB + _s * 8]), _ah + (size_t)_r * EDIM + _s * 8); \
    } \
    if (two_pass) { \
        const __half* _al = Alb + (size_t)_kc * BKC; \
        _Pragma("unroll") \
        for (int _i = 0; _i < 8; _i++) { \
            int _idx = tid + _i * 256; int _r = _idx >> 3, _s = _idx & 7; \
            cp_async16(smem_to_u32(&_sa[A2OFF + _r * LDSB + _s * 8]), _al + (size_t)_r * EDIM + _s * 8); \
        } \
    } \
    _Pragma("unroll") \
    for (int _i = 0; _i < 4; _i++) { \
        int _idx = tid + _i * 256; int _r = _idx >> 3, _s = _idx & 7; \
        cp_async16(smem_to_u32(&_sa[WFOFF + _r * LDSB + _s * 8]), _wf + (size_t)_r * EDIM + _s * 8); \
    } \
} while (0)

    const int NCH = EDIM / BKC;          // 16
    LOADC(0, 0); CP_COMMIT();

    for (int c = 0; c < NCH; c++) {
        CP_WAIT0();
        __syncthreads();
        if (c + 1 < NCH) { LOADC(c + 1, (c + 1) & 1); CP_COMMIT(); }

        const __half* st = gsm + (c & 1) * STAGE;
#pragma unroll
        for (int ks = 0; ks < 4; ks++) {
            const int k0 = ks * 16;
            uint32_t wf2[8][2];
#pragma unroll
            for (int p = 0; p < 4; p++) {
                uint32_t base = (wn + p * 16 + b_nin) * LDSB + k0 + b_ch * 8;
                uint32_t r0, r1, r2, r3;
                ldsm4(r0, r1, r2, r3, smem_to_u32(&st[WFOFF + base]));
                wf2[2*p][0] = r0; wf2[2*p][1] = r1; wf2[2*p+1][0] = r2; wf2[2*p+1][1] = r3;
            }
#pragma unroll
            for (int mt = 0; mt < 4; mt++) {
                uint32_t ahf[4];
                uint32_t base = (wm + mt * 16 + a_row) * LDSB + k0 + a_ch * 8;
                ldsm4(ahf[0], ahf[1], ahf[2], ahf[3], smem_to_u32(&st[base]));
#pragma unroll
                for (int nt = 0; nt < 8; nt++)
                    mma16816h(acc[mt][nt], ahf[0], ahf[1], ahf[2], ahf[3],
                              wf2[nt][0], wf2[nt][1]);
                if (two_pass) {
                    uint32_t alf[4];
                    ldsm4(alf[0], alf[1], alf[2], alf[3], smem_to_u32(&st[A2OFF + base]));
#pragma unroll
                    for (int nt = 0; nt < 8; nt++)
                        mma16816h(acc[mt][nt], alf[0], alf[1], alf[2], alf[3],
                                  wf2[nt][0], wf2[nt][1]);
                }
            }
        }
    }
#undef LOADC

    if (fp16out) {
        __half* O = (z == 0) ? O0 : (z == 1) ? O1 : O2;
#pragma unroll
        for (int nt = 0; nt < 8; nt++) {
            const int col = bn + wn + nt * 8 + (lane & 3) * 2;
            const float c0 = bias[col], c1 = bias[col + 1];
#pragma unroll
            for (int mt = 0; mt < 4; mt++) {
                const int r0 = bm + wm + mt * 16 + (lane >> 2);
#pragma unroll
                for (int rr = 0; rr < 2; rr++) {
                    float vx = (acc[mt][nt][2*rr+0] + c0) * scale;
                    float vy = (acc[mt][nt][2*rr+1] + c1) * scale;
                    size_t off = (size_t)(r0 + rr*8) * EDIM + col;
                    *(uint32_t*)(O + off) = packh2(vx, vy);
                }
            }
        }
    } else {
#pragma unroll
        for (int nt = 0; nt < 8; nt++) {
            const int col = bn + wn + nt * 8 + (lane & 3) * 2;
            const float c0 = bias[col], c1 = bias[col + 1];
#pragma unroll
            for (int mt = 0; mt < 4; mt++) {
                const int r0 = bm + wm + mt * 16 + (lane >> 2);
                *(float2*)&Cf[(size_t)r0 * EDIM + col] =
                    make_float2((acc[mt][nt][0] + c0) * scale, (acc[mt][nt][1] + c1) * scale);
                *(float2*)&Cf[(size_t)(r0 + 8) * EDIM + col] =
                    make_float2((acc[mt][nt][2] + c0) * scale, (acc[mt][nt][3] + c1) * scale);
            }
        }
    }
}

// ---------------- sliding-window flash attention, fp16 (S 1-pass, PV 2-pass) ----
#define ALDA 72
#define ATT_SMEM ((64 + 2*2*64) * ALDA * 2)   // 46,080 B

__global__ __launch_bounds__(128, 2)
void swattn_tc(const __half* __restrict__ Qf, const __half* __restrict__ Kf,
               const __half* __restrict__ Vf, __half* __restrict__ Of)
{
    extern __shared__ __align__(16) __half sb[];
    __half* Qs = sb;
    __half* KV = Qs + 64 * ALDA;

    const int tid = threadIdx.x, wid = tid >> 5, lane = tid & 31;
    const int qt = blockIdx.x, h = blockIdx.y, b = blockIdx.z;
    const int q0 = qt * 64;
    const size_t base = (size_t)b * SEQ * EDIM + (size_t)h * HD;
    const int kb0 = (qt > 4) ? qt - 4 : 0;
    const int NB  = qt - kb0 + 1;

#pragma unroll
    for (int i = 0; i < 4; i++) {
        int idx = tid + i * 128;
        int r = idx >> 3, s = idx & 7;
        cp_async16(smem_to_u32(Qs + r * ALDA + s * 8),
                   Qf + base + (size_t)(q0 + r) * EDIM + s * 8);
    }
    CP_COMMIT();

#define ALOAD_KV(kb, buf) do { \
    const __half* _srcs[2] = {Kf, Vf}; \
    __half* _d = KV + (buf) * 2 * 64 * ALDA; \
    _Pragma("unroll") \
    for (int _i = 0; _i < 8; _i++) { \
        int _idx = tid + _i * 128; \
        int _t = _idx >> 9, _r = (_idx >> 3) & 63, _s = _idx & 7; \
        cp_async16(smem_to_u32(_d + _t * 64 * ALDA + _r * ALDA + _s * 8), \
                   _srcs[_t] + base + (size_t)((kb) * 64 + _r) * EDIM + _s * 8); \
    } \
} while (0)

    ALOAD_KV(kb0, 0); CP_COMMIT();
    if (NB >= 2) { ALOAD_KV(kb0 + 1, 1); CP_COMMIT(); }

    const int b_nin = (lane & 7) + ((lane >= 16) ? 8 : 0);
    const int b_ch  = (lane >> 3) & 1;

    uint32_t qf[4][4];
    float o[8][4];
#pragma unroll
    for (int nt = 0; nt < 8; nt++)
#pragma unroll
        for (int j = 0; j < 4; j++) o[nt][j] = 0.f;
    float m0 = -1e30f, m1 = -1e30f, l0 = 0.f, l1 = 0.f;
    const int i0 = q0 + wid * 16 + (lane >> 2);

    for (int j = 0; j < NB; j++) {
        if (j + 1 < NB) CP_WAIT1(); else CP_WAIT0();
        __syncthreads();
        if (j == 0) {
#pragma unroll
            for (int kt = 0; kt < 4; kt++) {
                uint32_t a = smem_to_u32(&Qs[(wid*16 + (lane & 15)) * ALDA + kt*16 + (lane >> 4)*8]);
                ldsm4(qf[kt][0], qf[kt][1], qf[kt][2], qf[kt][3], a);
            }
        }
        const int kb = kb0 + j;
        const __half* khs = KV + (j & 1) * 2 * 64 * ALDA;
        const __half* vhs = khs + 64 * ALDA;

        float s[8][4];
#pragma unroll
        for (int nt = 0; nt < 8; nt++)
#pragma unroll
            for (int c = 0; c < 4; c++) s[nt][c] = 0.f;

#pragma unroll
        for (int kt = 0; kt < 4; kt++) {
            uint32_t bk[8][2];
#pragma unroll
            for (int p = 0; p < 4; p++) {
                uint32_t r0, r1, r2, r3;
                uint32_t addr = smem_to_u32(&khs[(p*16 + b_nin) * ALDA + kt*16 + b_ch*8]);
                ldsm4(r0, r1, r2, r3, addr);
                bk[2*p][0] = r0; bk[2*p][1] = r1; bk[2*p+1][0] = r2; bk[2*p+1][1] = r3;
            }
#pragma unroll
            for (int nt = 0; nt < 8; nt++)
                mma16816h(s[nt], qf[kt][0], qf[kt][1], qf[kt][2], qf[kt][3],
                          bk[nt][0], bk[nt][1]);
        }

        float mxA = -1e30f, mxB = -1e30f;
#pragma unroll
        for (int nt = 0; nt < 8; nt++) {
            int jb = kb * 64 + nt * 8 + (lane & 3) * 2;
            int d0 = i0 - jb;
            if ((unsigned)d0       > 256u) s[nt][0] = -1e30f;
            if ((unsigned)(d0 - 1) > 256u) s[nt][1] = -1e30f;
            if ((unsigned)(d0 + 8) > 256u) s[nt][2] = -1e30f;
            if ((unsigned)(d0 + 7) > 256u) s[nt][3] = -1e30f;
            mxA = fmaxf(mxA, fmaxf(s[nt][0], s[nt][1]));
            mxB = fmaxf(mxB, fmaxf(s[nt][2], s[nt][3]));
        }
        mxA = fmaxf(mxA, __shfl_xor_sync(0xffffffffu, mxA, 1));
        mxA = fmaxf(mxA, __shfl_xor_sync(0xffffffffu, mxA, 2));
        mxB = fmaxf(mxB, __shfl_xor_sync(0xffffffffu, mxB, 1));
        mxB = fmaxf(mxB, __shfl_xor_sync(0xffffffffu, mxB, 2));
        float nm0 = fmaxf(m0, mxA), nm1 = fmaxf(m1, mxB);
        float al0 = __expf(m0 - nm0), al1 = __expf(m1 - nm1);
        m0 = nm0; m1 = nm1;
        float rs0 = 0.f, rs1 = 0.f;
#pragma unroll
        for (int nt = 0; nt < 8; nt++) {
            s[nt][0] = __expf(s[nt][0] - m0);
            s[nt][1] = __expf(s[nt][1] - m0);
            s[nt][2] = __expf(s[nt][2] - m1);
            s[nt][3] = __expf(s[nt][3] - m1);
            rs0 += s[nt][0] + s[nt][1];
            rs1 += s[nt][2] + s[nt][3];
            o[nt][0] *= al0; o[nt][1] *= al0; o[nt][2] *= al1; o[nt][3] *= al1;
        }
        rs0 += __shfl_xor_sync(0xffffffffu, rs0, 1);
        rs0 += __shfl_xor_sync(0xffffffffu, rs0, 2);
        rs1 += __shfl_xor_sync(0xffffffffu, rs1, 1);
        rs1 += __shfl_xor_sync(0xffffffffu, rs1, 2);
        l0 = l0 * al0 + rs0;
        l1 = l1 * al1 + rs1;

#pragma unroll
        for (int kt = 0; kt < 4; kt++) {
            uint32_t pha[4], pla[4];
            {
                const int t0 = 2 * kt, t1 = 2 * kt + 1;
                __half h00 = __float2half_rn(s[t0][0]);
                __half h01 = __float2half_rn(s[t0][1]);
                __half h02 = __float2half_rn(s[t0][2]);
                __half h03 = __float2half_rn(s[t0][3]);
                __half h10 = __float2half_rn(s[t1][0]);
                __half h11 = __float2half_rn(s[t1][1]);
                __half h12 = __float2half_rn(s[t1][2]);
                __half h13 = __float2half_rn(s[t1][3]);
                pha[0] = ((uint32_t)*(uint16_t*)&h01 << 16) | *(uint16_t*)&h00;
                pha[1] = ((uint32_t)*(uint16_t*)&h03 << 16) | *(uint16_t*)&h02;
                pha[2] = ((uint32_t)*(uint16_t*)&h11 << 16) | *(uint16_t*)&h10;
                pha[3] = ((uint32_t)*(uint16_t*)&h13 << 16) | *(uint16_t*)&h12;
                pla[0] = packh2(s[t0][0] - __half2float(h00), s[t0][1] - __half2float(h01));
                pla[1] = packh2(s[t0][2] - __half2float(h02), s[t0][3] - __half2float(h03));
                pla[2] = packh2(s[t1][0] - __half2float(h10), s[t1][1] - __half2float(h11));
                pla[3] = packh2(s[t1][2] - __half2float(h12), s[t1][3] - __half2float(h13));
            }
#pragma unroll
            for (int p = 0; p < 4; p++) {
                uint32_t vrow = (kt*16 + ((lane >> 3) & 1)*8 + (lane & 7)) * ALDA + (p*2 + (lane >> 4))*8;
                uint32_t r0, r1, r2, r3;
                ldsm4t(r0, r1, r2, r3, smem_to_u32(&vhs[vrow]));
                mma16816h(o[2*p],   pha[0], pha[1], pha[2], pha[3], r0, r1);
                mma16816h(o[2*p],   pla[0], pla[1], pla[2], pla[3], r0, r1);
                mma16816h(o[2*p+1], pha[0], pha[1], pha[2], pha[3], r2, r3);
                mma16816h(o[2*p+1], pla[0], pla[1], pla[2], pla[3], r2, r3);
            }
        }

        __syncthreads();
        if (j + 2 < NB) { ALOAD_KV(kb0 + j + 2, j & 1); CP_COMMIT(); }
    }
#undef ALOAD_KV

    // epilogue: single fp16 y
    const float inv0 = 1.0f / l0, inv1 = 1.0f / l1;
#pragma unroll
    for (int nt = 0; nt < 8; nt++) {
        const int col = nt * 8 + (lane & 3) * 2;
        size_t off0 = base + (size_t)i0 * EDIM + col;
        size_t off1 = base + (size_t)(i0 + 8) * EDIM + col;
        *(uint32_t*)(Of + off0) = packh2(o[nt][0] * inv0, o[nt][1] * inv0);
        *(uint32_t*)(Of + off1) = packh2(o[nt][2] * inv1, o[nt][3] * inv1);
    }
}

// ---------------- launch ----------------
extern "C" void kernel_launch(void* const* d_in, const int* in_sizes, int n_in,
                              void* d_out, int out_size)
{
    const float* x  = (const float*)d_in[0];
    const float* Wq = (const float*)d_in[1];
    const float* Wk = (const float*)d_in[2];
    const float* Wv = (const float*)d_in[3];
    const float* Wo = (const float*)d_in[4];
    const float* bq = (const float*)d_in[5];
    const float* bk = (const float*)d_in[6];
    const float* bv = (const float*)d_in[7];
    const float* bo = (const float*)d_in[8];

    __half *xf, *qf, *kf, *vf, *yf, *wf;
    cudaGetSymbolAddress((void**)&xf, g_xf);
    cudaGetSymbolAddress((void**)&qf, g_qf);
    cudaGetSymbolAddress((void**)&kf, g_kf);
    cudaGetSymbolAddress((void**)&vf, g_vf);
    cudaGetSymbolAddress((void**)&yf, g_yf);
    cudaGetSymbolAddress((void**)&wf, g_wf);

    static bool attr_done = false;
    if (!attr_done) {
        cudaFuncSetAttribute(gemm_tc2,  cudaFuncAttributeMaxDynamicSharedMemorySize, GEMM_SMEM);
        cudaFuncSetAttribute(swattn_tc, cudaFuncAttributeMaxDynamicSharedMemorySize, ATT_SMEM);
        attr_done = true;
    }

    const int NX4 = MROWS * EDIM / 4;   // 1,048,576
    const int NW4 = EDIM * EDIM / 4;    //   262,144
    const size_t WSZ = (size_t)EDIM * EDIM;

    split5<<<dim3((NX4 + 255) / 256, 5), 256>>>(
        x, Wq, Wk, Wv, Wo, xf, wf, NX4, NW4);

    // fused QKV projection: 1-pass fp16 (q pre-scaled by 1/8)
    gemm_tc2<<<dim3(EDIM/BN, MROWS/BM, 3), 256, GEMM_SMEM>>>(
        xf, nullptr, wf, bq, bk, bv, nullptr,
        qf, kf, vf, 0.125f, 1, 0);

    swattn_tc<<<dim3(SEQ/64, HEADS, BATCH), 128, ATT_SMEM>>>(
        qf, kf, vf, yf);

    // output projection: 1-pass fp16 y -> fp32 d_out
    gemm_tc2<<<dim3(EDIM/BN, MROWS/BM, 1), 256, GEMM_SMEM>>>(
        yf, nullptr, wf + 3*WSZ, bo, nullptr, nullptr,
        (float*)d_out, nullptr, nullptr, nullptr, 1.0f, 0, 0);
}

// round 16
// speedup vs baseline: 2.4522x; 1.0101x over previous
#include <cuda_runtime.h>
#include <cuda_bf16.h>
#include <cuda_fp16.h>
#include <cstdint>

#define EDIM  1024
#define HEADS 16
#define HD    64
#define WIN   256
#define BATCH 2
#define SEQ   2048
#define MROWS (BATCH*SEQ)   // 4096

// ---------------- scratch (allocation-free rule: device globals) ----------------
static __device__ __half g_xf[MROWS*EDIM];
static __device__ __half g_qf[MROWS*EDIM];
static __device__ __half g_kf[MROWS*EDIM];
static __device__ __half g_vf[MROWS*EDIM];
static __device__ __half g_yf[MROWS*EDIM];
static __device__ __half g_wf[4][EDIM*EDIM];

// ---------------- family-common PTX helpers ----------------
__device__ __forceinline__ uint32_t smem_to_u32(const void* p) {
    uint32_t a;
    asm("{ .reg .u64 t; cvta.to.shared.u64 t, %1; cvt.u32.u64 %0, t; }"
        : "=r"(a) : "l"(p));
    return a;
}
__device__ __forceinline__ void cp_async16(uint32_t dst, const void* src) {
    asm volatile("cp.async.cg.shared.global [%0], [%1], 16;" :: "r"(dst), "l"(src));
}
#define CP_COMMIT() asm volatile("cp.async.commit_group;" ::: "memory")
#define CP_WAIT1()  asm volatile("cp.async.wait_group 1;" ::: "memory")
#define CP_WAIT0()  asm volatile("cp.async.wait_group 0;" ::: "memory")

__device__ __forceinline__ void ldsm4(uint32_t& r0, uint32_t& r1, uint32_t& r2,
                                      uint32_t& r3, uint32_t addr) {
    asm volatile("ldmatrix.sync.aligned.m8n8.x4.shared.b16 {%0,%1,%2,%3}, [%4];"
                 : "=r"(r0), "=r"(r1), "=r"(r2), "=r"(r3) : "r"(addr));
}
__device__ __forceinline__ void ldsm4t(uint32_t& r0, uint32_t& r1, uint32_t& r2,
                                       uint32_t& r3, uint32_t addr) {
    asm volatile("ldmatrix.sync.aligned.m8n8.x4.trans.shared.b16 {%0,%1,%2,%3}, [%4];"
                 : "=r"(r0), "=r"(r1), "=r"(r2), "=r"(r3) : "r"(addr));
}
__device__ __forceinline__ void mma16816h(float* c, uint32_t a0, uint32_t a1,
                                          uint32_t a2, uint32_t a3,
                                          uint32_t b0, uint32_t b1) {
    asm volatile(
        "mma.sync.aligned.m16n8k16.row.col.f32.f16.f16.f32 "
        "{%0,%1,%2,%3}, {%4,%5,%6,%7}, {%8,%9}, {%0,%1,%2,%3};"
        : "+f"(c[0]), "+f"(c[1]), "+f"(c[2]), "+f"(c[3])
        : "r"(a0), "r"(a1), "r"(a2), "r"(a3), "r"(b0), "r"(b1));
}
__device__ __forceinline__ uint32_t packh2(float a, float b) {
    __half2 t = __floats2half2_rn(a, b);
    return *(uint32_t*)&t;
}

// ---------------- fused fp32 -> fp16 convert (x and 4 W slabs) ----
__global__ __launch_bounds__(256)
void split5(const float* __restrict__ s0, const float* __restrict__ s1,
            const float* __restrict__ s2, const float* __restrict__ s3,
            const float* __restrict__ s4,
            __half* __restrict__ xf, __half* __restrict__ wf, int n0, int nw)
{
    const int t = blockIdx.y;
    const int n4 = (t == 0) ? n0 : nw;
    int i = blockIdx.x * 256 + threadIdx.x;
    if (i >= n4) return;
    const float* in = (t == 0) ? s0 : (t == 1) ? s1 : (t == 2) ? s2 : (t == 3) ? s3 : s4;
    float4 v = ((const float4*)in)[i];
    float vv[4] = {v.x, v.y, v.z, v.w};
    __half h[4];
#pragma unroll
    for (int j = 0; j < 4; j++) h[j] = __float2half_rn(vv[j]);
    __half* dst = (t == 0) ? xf : (wf + (size_t)(t - 1) * EDIM * EDIM);
    ((uint2*)dst)[i] = *(uint2*)h;
}

// ---------------- fp16 warp-MMA GEMM, 1-pass, BKC=128 (8 chunks) --------------
#define BM   256
#define BN   128
#define BKC  128
#define LDSB 136                          // 128 cols + 8 pad (conflict-free ldsm)
#define WFOFF (256*LDSB)
#define STAGE (384*LDSB)                  // elements per stage (52224)
#define GEMM_SMEM (2*STAGE*2)             // 208,896 B -> 1 CTA/SM, 8 warps

__global__ __launch_bounds__(256, 1)
void gemm_tc2(const __half* __restrict__ Af, const __half* __restrict__ Wf,
              const float* __restrict__ b0v, const float* __restrict__ b1v,
              const float* __restrict__ b2v,
              float* __restrict__ Cf,
              __half* __restrict__ O0, __half* __restrict__ O1, __half* __restrict__ O2,
              float s0, int fp16out)
{
    extern __shared__ __align__(16) __half gsm[];

    const int tid  = threadIdx.x;
    const int wid  = tid >> 5;
    const int lane = tid & 31;
    const int bm   = blockIdx.y * BM;
    const int bn   = blockIdx.x * BN;
    const int z    = blockIdx.z;
    const int wm   = (wid & 3) * 64;
    const int wn   = (wid >> 2) * 64;

    const __half* Wfb = Wf + (size_t)z * EDIM * EDIM + (size_t)bn * EDIM;
    const __half* Afb = Af + (size_t)bm * EDIM;
    const float* bias = (z == 0) ? b0v : (z == 1) ? b1v : b2v;
    const float scale = (z == 0) ? s0 : 1.0f;

    float acc[4][8][4];
#pragma unroll
    for (int mt = 0; mt < 4; mt++)
#pragma unroll
        for (int nt = 0; nt < 8; nt++)
#pragma unroll
            for (int j = 0; j < 4; j++) acc[mt][nt][j] = 0.f;

    const int a_row = lane & 15, a_ch = lane >> 4;
    const int b_nin = (lane & 7) + ((lane >= 16) ? 8 : 0);
    const int b_ch  = (lane >> 3) & 1;

// one chunk (k128): A 256x128 (16 segs/thread), W 128x128 (8 segs/thread)
#define LOADC(cc, st) do { \
    const int _kc = (cc); \
    __half* _sa = gsm + (st) * STAGE; \
    const __half* _af = Afb + (size_t)_kc * BKC; \
    const __half* _wf = Wfb + (size_t)_kc * BKC; \
    _Pragma("unroll") \
    for (int _i = 0; _i < 16; _i++) { \
        int _idx = tid + _i * 256; int _r = _idx >> 4, _s = _idx & 15; \
        cp_async16(smem_to_u32(&_sa[_r * LDSB + _s * 8]), _af + (size_t)_r * EDIM + _s * 8); \
    } \
    _Pragma("unroll") \
    for (int _i = 0; _i < 8; _i++) { \
        int _idx = tid + _i * 256; int _r = _idx >> 4, _s = _idx & 15; \
        cp_async16(smem_to_u32(&_sa[WFOFF + _r * LDSB + _s * 8]), _wf + (size_t)_r * EDIM + _s * 8); \
    } \
} while (0)

    const int NCH = EDIM / BKC;          // 8
    LOADC(0, 0); CP_COMMIT();

    for (int c = 0; c < NCH; c++) {
        CP_WAIT0();
        __syncthreads();
        if (c + 1 < NCH) { LOADC(c + 1, (c + 1) & 1); CP_COMMIT(); }

        const __half* st = gsm + (c & 1) * STAGE;
#pragma unroll
        for (int ks = 0; ks < 8; ks++) {
            const int k0 = ks * 16;
            uint32_t wf2[8][2];
#pragma unroll
            for (int p = 0; p < 4; p++) {
                uint32_t base = (wn + p * 16 + b_nin) * LDSB + k0 + b_ch * 8;
                uint32_t r0, r1, r2, r3;
                ldsm4(r0, r1, r2, r3, smem_to_u32(&st[WFOFF + base]));
                wf2[2*p][0] = r0; wf2[2*p][1] = r1; wf2[2*p+1][0] = r2; wf2[2*p+1][1] = r3;
            }
#pragma unroll
            for (int mt = 0; mt < 4; mt++) {
                uint32_t af4[4];
                uint32_t base = (wm + mt * 16 + a_row) * LDSB + k0 + a_ch * 8;
                ldsm4(af4[0], af4[1], af4[2], af4[3], smem_to_u32(&st[base]));
#pragma unroll
                for (int nt = 0; nt < 8; nt++)
                    mma16816h(acc[mt][nt], af4[0], af4[1], af4[2], af4[3],
                              wf2[nt][0], wf2[nt][1]);
            }
        }
    }
#undef LOADC

    if (fp16out) {
        __half* O = (z == 0) ? O0 : (z == 1) ? O1 : O2;
#pragma unroll
        for (int nt = 0; nt < 8; nt++) {
            const int col = bn + wn + nt * 8 + (lane & 3) * 2;
            const float c0 = bias[col], c1 = bias[col + 1];
#pragma unroll
            for (int mt = 0; mt < 4; mt++) {
                const int r0 = bm + wm + mt * 16 + (lane >> 2);
#pragma unroll
                for (int rr = 0; rr < 2; rr++) {
                    float vx = (acc[mt][nt][2*rr+0] + c0) * scale;
                    float vy = (acc[mt][nt][2*rr+1] + c1) * scale;
                    size_t off = (size_t)(r0 + rr*8) * EDIM + col;
                    *(uint32_t*)(O + off) = packh2(vx, vy);
                }
            }
        }
    } else {
#pragma unroll
        for (int nt = 0; nt < 8; nt++) {
            const int col = bn + wn + nt * 8 + (lane & 3) * 2;
            const float c0 = bias[col], c1 = bias[col + 1];
#pragma unroll
            for (int mt = 0; mt < 4; mt++) {
                const int r0 = bm + wm + mt * 16 + (lane >> 2);
                *(float2*)&Cf[(size_t)r0 * EDIM + col] =
                    make_float2((acc[mt][nt][0] + c0) * scale, (acc[mt][nt][1] + c1) * scale);
                *(float2*)&Cf[(size_t)(r0 + 8) * EDIM + col] =
                    make_float2((acc[mt][nt][2] + c0) * scale, (acc[mt][nt][3] + c1) * scale);
            }
        }
    }
}

// ---------------- sliding-window flash attention, fp16 (S 1-pass, PV 2-pass) ----
#define ALDA 72
#define ATT_SMEM ((64 + 2*2*64) * ALDA * 2)   // 46,080 B

__global__ __launch_bounds__(128, 2)
void swattn_tc(const __half* __restrict__ Qf, const __half* __restrict__ Kf,
               const __half* __restrict__ Vf, __half* __restrict__ Of)
{
    extern __shared__ __align__(16) __half sb[];
    __half* Qs = sb;
    __half* KV = Qs + 64 * ALDA;

    const int tid = threadIdx.x, wid = tid >> 5, lane = tid & 31;
    const int qt = blockIdx.x, h = blockIdx.y, b = blockIdx.z;
    const int q0 = qt * 64;
    const size_t base = (size_t)b * SEQ * EDIM + (size_t)h * HD;
    const int kb0 = (qt > 4) ? qt - 4 : 0;
    const int NB  = qt - kb0 + 1;

#pragma unroll
    for (int i = 0; i < 4; i++) {
        int idx = tid + i * 128;
        int r = idx >> 3, s = idx & 7;
        cp_async16(smem_to_u32(Qs + r * ALDA + s * 8),
                   Qf + base + (size_t)(q0 + r) * EDIM + s * 8);
    }
    CP_COMMIT();

#define ALOAD_KV(kb, buf) do { \
    const __half* _srcs[2] = {Kf, Vf}; \
    __half* _d = KV + (buf) * 2 * 64 * ALDA; \
    _Pragma("unroll") \
    for (int _i = 0; _i < 8; _i++) { \
        int _idx = tid + _i * 128; \
        int _t = _idx >> 9, _r = (_idx >> 3) & 63, _s = _idx & 7; \
        cp_async16(smem_to_u32(_d + _t * 64 * ALDA + _r * ALDA + _s * 8), \
                   _srcs[_t] + base + (size_t)((kb) * 64 + _r) * EDIM + _s * 8); \
    } \
} while (0)

    ALOAD_KV(kb0, 0); CP_COMMIT();
    if (NB >= 2) { ALOAD_KV(kb0 + 1, 1); CP_COMMIT(); }

    const int b_nin = (lane & 7) + ((lane >= 16) ? 8 : 0);
    const int b_ch  = (lane >> 3) & 1;

    uint32_t qf[4][4];
    float o[8][4];
#pragma unroll
    for (int nt = 0; nt < 8; nt++)
#pragma unroll
        for (int j = 0; j < 4; j++) o[nt][j] = 0.f;
    float m0 = -1e30f, m1 = -1e30f, l0 = 0.f, l1 = 0.f;
    const int i0 = q0 + wid * 16 + (lane >> 2);

    for (int j = 0; j < NB; j++) {
        if (j + 1 < NB) CP_WAIT1(); else CP_WAIT0();
        __syncthreads();
        if (j == 0) {
#pragma unroll
            for (int kt = 0; kt < 4; kt++) {
                uint32_t a = smem_to_u32(&Qs[(wid*16 + (lane & 15)) * ALDA + kt*16 + (lane >> 4)*8]);
                ldsm4(qf[kt][0], qf[kt][1], qf[kt][2], qf[kt][3], a);
            }
        }
        const int kb = kb0 + j;
        const __half* khs = KV + (j & 1) * 2 * 64 * ALDA;
        const __half* vhs = khs + 64 * ALDA;

        float s[8][4];
#pragma unroll
        for (int nt = 0; nt < 8; nt++)
#pragma unroll
            for (int c = 0; c < 4; c++) s[nt][c] = 0.f;

#pragma unroll
        for (int kt = 0; kt < 4; kt++) {
            uint32_t bk[8][2];
#pragma unroll
            for (int p = 0; p < 4; p++) {
                uint32_t r0, r1, r2, r3;
                uint32_t addr = smem_to_u32(&khs[(p*16 + b_nin) * ALDA + kt*16 + b_ch*8]);
                ldsm4(r0, r1, r2, r3, addr);
                bk[2*p][0] = r0; bk[2*p][1] = r1; bk[2*p+1][0] = r2; bk[2*p+1][1] = r3;
            }
#pragma unroll
            for (int nt = 0; nt < 8; nt++)
                mma16816h(s[nt], qf[kt][0], qf[kt][1], qf[kt][2], qf[kt][3],
                          bk[nt][0], bk[nt][1]);
        }

        float mxA = -1e30f, mxB = -1e30f;
#pragma unroll
        for (int nt = 0; nt < 8; nt++) {
            int jb = kb * 64 + nt * 8 + (lane & 3) * 2;
            int d0 = i0 - jb;
            if ((unsigned)d0       > 256u) s[nt][0] = -1e30f;
            if ((unsigned)(d0 - 1) > 256u) s[nt][1] = -1e30f;
            if ((unsigned)(d0 + 8) > 256u) s[nt][2] = -1e30f;
            if ((unsigned)(d0 + 7) > 256u) s[nt][3] = -1e30f;
            mxA = fmaxf(mxA, fmaxf(s[nt][0], s[nt][1]));
            mxB = fmaxf(mxB, fmaxf(s[nt][2], s[nt][3]));
        }
        mxA = fmaxf(mxA, __shfl_xor_sync(0xffffffffu, mxA, 1));
        mxA = fmaxf(mxA, __shfl_xor_sync(0xffffffffu, mxA, 2));
        mxB = fmaxf(mxB, __shfl_xor_sync(0xffffffffu, mxB, 1));
        mxB = fmaxf(mxB, __shfl_xor_sync(0xffffffffu, mxB, 2));
        float nm0 = fmaxf(m0, mxA), nm1 = fmaxf(m1, mxB);
        float al0 = __expf(m0 - nm0), al1 = __expf(m1 - nm1);
        m0 = nm0; m1 = nm1;
        float rs0 = 0.f, rs1 = 0.f;
#pragma unroll
        for (int nt = 0; nt < 8; nt++) {
            s[nt][0] = __expf(s[nt][0] - m0);
            s[nt][1] = __expf(s[nt][1] - m0);
            s[nt][2] = __expf(s[nt][2] - m1);
            s[nt][3] = __expf(s[nt][3] - m1);
            rs0 += s[nt][0] + s[nt][1];
            rs1 += s[nt][2] + s[nt][3];
            o[nt][0] *= al0; o[nt][1] *= al0; o[nt][2] *= al1; o[nt][3] *= al1;
        }
        rs0 += __shfl_xor_sync(0xffffffffu, rs0, 1);
        rs0 += __shfl_xor_sync(0xffffffffu, rs0, 2);
        rs1 += __shfl_xor_sync(0xffffffffu, rs1, 1);
        rs1 += __shfl_xor_sync(0xffffffffu, rs1, 2);
        l0 = l0 * al0 + rs0;
        l1 = l1 * al1 + rs1;

#pragma unroll
        for (int kt = 0; kt < 4; kt++) {
            uint32_t pha[4], pla[4];
            {
                const int t0 = 2 * kt, t1 = 2 * kt + 1;
                __half h00 = __float2half_rn(s[t0][0]);
                __half h01 = __float2half_rn(s[t0][1]);
                __half h02 = __float2half_rn(s[t0][2]);
                __half h03 = __float2half_rn(s[t0][3]);
                __half h10 = __float2half_rn(s[t1][0]);
                __half h11 = __float2half_rn(s[t1][1]);
                __half h12 = __float2half_rn(s[t1][2]);
                __half h13 = __float2half_rn(s[t1][3]);
                pha[0] = ((uint32_t)*(uint16_t*)&h01 << 16) | *(uint16_t*)&h00;
                pha[1] = ((uint32_t)*(uint16_t*)&h03 << 16) | *(uint16_t*)&h02;
                pha[2] = ((uint32_t)*(uint16_t*)&h11 << 16) | *(uint16_t*)&h10;
                pha[3] = ((uint32_t)*(uint16_t*)&h13 << 16) | *(uint16_t*)&h12;
                pla[0] = packh2(s[t0][0] - __half2float(h00), s[t0][1] - __half2float(h01));
                pla[1] = packh2(s[t0][2] - __half2float(h02), s[t0][3] - __half2float(h03));
                pla[2] = packh2(s[t1][0] - __half2float(h10), s[t1][1] - __half2float(h11));
                pla[3] = packh2(s[t1][2] - __half2float(h12), s[t1][3] - __half2float(h13));
            }
#pragma unroll
            for (int p = 0; p < 4; p++) {
                uint32_t vrow = (kt*16 + ((lane >> 3) & 1)*8 + (lane & 7)) * ALDA + (p*2 + (lane >> 4))*8;
                uint32_t r0, r1, r2, r3;
                ldsm4t(r0, r1, r2, r3, smem_to_u32(&vhs[vrow]));
                mma16816h(o[2*p],   pha[0], pha[1], pha[2], pha[3], r0, r1);
                mma16816h(o[2*p],   pla[0], pla[1], pla[2], pla[3], r0, r1);
                mma16816h(o[2*p+1], pha[0], pha[1], pha[2], pha[3], r2, r3);
                mma16816h(o[2*p+1], pla[0], pla[1], pla[2], pla[3], r2, r3);
            }
        }

        __syncthreads();
        if (j + 2 < NB) { ALOAD_KV(kb0 + j + 2, j & 1); CP_COMMIT(); }
    }
#undef ALOAD_KV

    const float inv0 = 1.0f / l0, inv1 = 1.0f / l1;
#pragma unroll
    for (int nt = 0; nt < 8; nt++) {
        const int col = nt * 8 + (lane & 3) * 2;
        size_t off0 = base + (size_t)i0 * EDIM + col;
        size_t off1 = base + (size_t)(i0 + 8) * EDIM + col;
        *(uint32_t*)(Of + off0) = packh2(o[nt][0] * inv0, o[nt][1] * inv0);
        *(uint32_t*)(Of + off1) = packh2(o[nt][2] * inv1, o[nt][3] * inv1);
    }
}

// ---------------- launch ----------------
extern "C" void kernel_launch(void* const* d_in, const int* in_sizes, int n_in,
                              void* d_out, int out_size)
{
    const float* x  = (const float*)d_in[0];
    const float* Wq = (const float*)d_in[1];
    const float* Wk = (const float*)d_in[2];
    const float* Wv = (const float*)d_in[3];
    const float* Wo = (const float*)d_in[4];
    const float* bq = (const float*)d_in[5];
    const float* bk = (const float*)d_in[6];
    const float* bv = (const float*)d_in[7];
    const float* bo = (const float*)d_in[8];

    __half *xf, *qf, *kf, *vf, *yf, *wf;
    cudaGetSymbolAddress((void**)&xf, g_xf);
    cudaGetSymbolAddress((void**)&qf, g_qf);
    cudaGetSymbolAddress((void**)&kf, g_kf);
    cudaGetSymbolAddress((void**)&vf, g_vf);
    cudaGetSymbolAddress((void**)&yf, g_yf);
    cudaGetSymbolAddress((void**)&wf, g_wf);

    static bool attr_done = false;
    if (!attr_done) {
        cudaFuncSetAttribute(gemm_tc2,  cudaFuncAttributeMaxDynamicSharedMemorySize, GEMM_SMEM);
        cudaFuncSetAttribute(swattn_tc, cudaFuncAttributeMaxDynamicSharedMemorySize, ATT_SMEM);
        attr_done = true;
    }

    const int NX4 = MROWS * EDIM / 4;   // 1,048,576
    const int NW4 = EDIM * EDIM / 4;    //   262,144
    const size_t WSZ = (size_t)EDIM * EDIM;

    split5<<<dim3((NX4 + 255) / 256, 5), 256>>>(
        x, Wq, Wk, Wv, Wo, xf, wf, NX4, NW4);

    // fused QKV projection: 1-pass fp16 (q pre-scaled by 1/8)
    gemm_tc2<<<dim3(EDIM/BN, MROWS/BM, 3), 256, GEMM_SMEM>>>(
        xf, wf, bq, bk, bv, nullptr,
        qf, kf, vf, 0.125f, 1);

    swattn_tc<<<dim3(SEQ/64, HEADS, BATCH), 128, ATT_SMEM>>>(
        qf, kf, vf, yf);

    // output projection: 1-pass fp16 y -> fp32 d_out
    gemm_tc2<<<dim3(EDIM/BN, MROWS/BM, 1), 256, GEMM_SMEM>>>(
        yf, wf + 3*WSZ, bo, nullptr, nullptr,
        (float*)d_out, nullptr, nullptr, nullptr, 1.0f, 0);
}